// round 1
// baseline (speedup 1.0000x reference)
#include <cuda_runtime.h>

#define B 8
#define C 256
#define L 2048
#define D 32

// Scratch (device globals — no cudaMalloc allowed)
__device__ float g_Q[B * L * D];   // [b][l][d]   2 MB
__device__ float g_K[B * L * D];   // [b][l][d]   2 MB
__device__ float g_V[B * L * C];   // [b][l][c]  16 MB

// ---------------------------------------------------------------------------
// packed fp32x2 math (FFMA2 / FMUL2 — only reachable via PTX on sm_103a)
// ---------------------------------------------------------------------------
union F2U { float2 f; unsigned long long u; };

__device__ __forceinline__ float2 ffma2(float2 a, float2 b, float2 c) {
    F2U A, Bv, Cv, Dv;
    A.f = a; Bv.f = b; Cv.f = c;
    asm("fma.rn.f32x2 %0, %1, %2, %3;" : "=l"(Dv.u) : "l"(A.u), "l"(Bv.u), "l"(Cv.u));
    return Dv.f;
}

__device__ __forceinline__ float2 fmul2(float2 a, float2 b) {
    F2U A, Bv, Dv;
    A.f = a; Bv.f = b;
    asm("mul.rn.f32x2 %0, %1, %2;" : "=l"(Dv.u) : "l"(A.u), "l"(Bv.u));
    return Dv.f;
}

// ---------------------------------------------------------------------------
// Kernel 1: QKV projection (1x1 conv == per-position matmul)
// grid (L/32, B), 256 threads. Block handles 32 positions x 320 output rows.
// ---------------------------------------------------------------------------
__global__ __launch_bounds__(256) void qkv_kernel(
    const float* __restrict__ x,
    const float* __restrict__ Wq, const float* __restrict__ bq,
    const float* __restrict__ Wk, const float* __restrict__ bk,
    const float* __restrict__ Wv, const float* __restrict__ bv)
{
    __shared__ float xs[32][260];   // [l][c], pad 260 -> conflict-free float4 reads

    const int b  = blockIdx.y;
    const int l0 = blockIdx.x * 32;
    const int t  = threadIdx.x;

    const float* xb = x + (size_t)b * C * L;
    // load x tile: consecutive threads -> consecutive l (coalesced gmem)
    for (int idx = t; idx < C * 32; idx += 256) {
        int c  = idx >> 5;
        int ll = idx & 31;
        xs[ll][c] = xb[(size_t)c * L + l0 + ll];
    }
    __syncthreads();

    const int w    = t >> 5;    // warp id: output-row group
    const int lane = t & 31;    // position within tile
    const float4* xp = reinterpret_cast<const float4*>(&xs[lane][0]);

    for (int it = 0; it < 40; ++it) {
        int row = it * 8 + w;   // uniform per warp
        const float* Wrow;
        float bias;
        float* dst;
        if (row < 32) {
            Wrow = Wq + row * C; bias = __ldg(&bq[row]);
            dst = &g_Q[((size_t)b * L + l0 + lane) * D + row];
        } else if (row < 64) {
            int d = row - 32;
            Wrow = Wk + d * C; bias = __ldg(&bk[d]);
            dst = &g_K[((size_t)b * L + l0 + lane) * D + d];
        } else {
            int o = row - 64;
            Wrow = Wv + o * C; bias = __ldg(&bv[o]);
            dst = &g_V[((size_t)b * L + l0 + lane) * C + o];
        }
        const float4* wp = reinterpret_cast<const float4*>(Wrow);
        float2 acc = make_float2(0.f, 0.f);
        #pragma unroll 16
        for (int c4 = 0; c4 < 64; ++c4) {
            float4 wv = __ldg(wp + c4);
            float4 xv = xp[c4];
            acc = ffma2(make_float2(wv.x, wv.y), make_float2(xv.x, xv.y), acc);
            acc = ffma2(make_float2(wv.z, wv.w), make_float2(xv.z, xv.w), acc);
        }
        *dst = acc.x + acc.y + bias;
    }
}

// ---------------------------------------------------------------------------
// Kernel 2: flash-style attention + fused epilogue (gamma*out + x)
// grid (L/64, B), 256 threads. Block: 64 queries x 256 channels.
// Thread owns (query i = t&63, channel group g = t>>6 -> 64 channels).
// ---------------------------------------------------------------------------
__global__ __launch_bounds__(256, 2) void attn_kernel(
    const float* __restrict__ x,
    const float* __restrict__ gamma,
    float* __restrict__ out)
{
    __shared__ float Ks[32][33];      // key chunk [j][d]
    __shared__ float Vs[32][256];     // value chunk [j][c]
    __shared__ float Ps[64][33];      // scores/probs [i][j]
    __shared__ float sm[64], sl[64], scorr[64];

    const int b  = blockIdx.y;
    const int i0 = blockIdx.x * 64;
    const int t  = threadIdx.x;
    const int i  = t & 63;
    const int g  = t >> 6;
    const int cbase = g * 64;

    // Q row for this thread's query: 32 floats, loaded once
    float4 qreg[8];
    {
        const float4* qp = reinterpret_cast<const float4*>(&g_Q[((size_t)b * L + i0 + i) * D]);
        #pragma unroll
        for (int k = 0; k < 8; ++k) qreg[k] = __ldg(qp + k);
    }

    if (t < 64) { sm[t] = -1e30f; sl[t] = 0.f; }

    float2 acc[32];
    #pragma unroll
    for (int k = 0; k < 32; ++k) acc[k] = make_float2(0.f, 0.f);

    const float scale = 0.17677669529663687f;  // 1/sqrt(32)
    const float* Kb = &g_K[(size_t)b * L * D];
    const float* Vb = &g_V[(size_t)b * L * C];

    for (int j0 = 0; j0 < L; j0 += 32) {
        __syncthreads();
        // load K chunk
        for (int idx = t; idx < 32 * 32; idx += 256) {
            int j = idx >> 5, d = idx & 31;
            Ks[j][d] = Kb[(size_t)(j0 + j) * D + d];
        }
        // load V chunk (float4, coalesced)
        {
            const float4* vsrc = reinterpret_cast<const float4*>(Vb + (size_t)j0 * C);
            float4* vdst = reinterpret_cast<float4*>(&Vs[0][0]);
            for (int idx = t; idx < 32 * 64; idx += 256) vdst[idx] = vsrc[idx];
        }
        __syncthreads();

        // S = Q K^T * scale : thread computes 8 j's for its query i
        {
            const int jb = g * 8;
            #pragma unroll
            for (int jj = 0; jj < 8; ++jj) {
                int j = jb + jj;
                const float4* kp = reinterpret_cast<const float4*>(&Ks[j][0]);
                float2 a2 = make_float2(0.f, 0.f);
                #pragma unroll
                for (int k = 0; k < 8; ++k) {
                    float4 kv = kp[k];
                    a2 = ffma2(make_float2(qreg[k].x, qreg[k].y), make_float2(kv.x, kv.y), a2);
                    a2 = ffma2(make_float2(qreg[k].z, qreg[k].w), make_float2(kv.z, kv.w), a2);
                }
                Ps[i][j] = (a2.x + a2.y) * scale;
            }
        }
        __syncthreads();

        // online softmax per query (threads 0..63)
        if (t < 64) {
            float mold = sm[t];
            float cmax = mold;
            #pragma unroll
            for (int j = 0; j < 32; ++j) cmax = fmaxf(cmax, Ps[t][j]);
            float corr = __expf(mold - cmax);
            float s = 0.f;
            #pragma unroll
            for (int j = 0; j < 32; ++j) {
                float p = __expf(Ps[t][j] - cmax);
                Ps[t][j] = p;
                s += p;
            }
            sm[t] = cmax;
            sl[t] = sl[t] * corr + s;
            scorr[t] = corr;
        }
        __syncthreads();

        // O update: rescale accumulators, accumulate P * V
        {
            float corr = scorr[i];
            float2 c2 = make_float2(corr, corr);
            #pragma unroll
            for (int k = 0; k < 32; ++k) acc[k] = fmul2(acc[k], c2);

            #pragma unroll 4
            for (int j = 0; j < 32; ++j) {
                float p = Ps[i][j];
                float2 p2 = make_float2(p, p);
                const float4* vrow = reinterpret_cast<const float4*>(&Vs[j][cbase]);
                #pragma unroll
                for (int k = 0; k < 16; ++k) {
                    float4 v = vrow[k];
                    acc[2 * k]     = ffma2(p2, make_float2(v.x, v.y), acc[2 * k]);
                    acc[2 * k + 1] = ffma2(p2, make_float2(v.z, v.w), acc[2 * k + 1]);
                }
            }
        }
    }

    // epilogue: out = gamma * (O / l) + x   (coalesced over i)
    const float linv = 1.f / sl[i];
    const float gam  = __ldg(gamma);
    float* ob       = out + (size_t)b * C * L;
    const float* xb = x   + (size_t)b * C * L;
    #pragma unroll
    for (int k = 0; k < 32; ++k) {
        int c0 = cbase + 2 * k;
        float o0 = gam * (acc[k].x * linv) + xb[(size_t)c0 * L + i0 + i];
        float o1 = gam * (acc[k].y * linv) + xb[(size_t)(c0 + 1) * L + i0 + i];
        ob[(size_t)c0 * L + i0 + i]       = o0;
        ob[(size_t)(c0 + 1) * L + i0 + i] = o1;
    }
}

// ---------------------------------------------------------------------------
extern "C" void kernel_launch(void* const* d_in, const int* in_sizes, int n_in,
                              void* d_out, int out_size)
{
    const float* x     = (const float*)d_in[0];
    const float* Wq    = (const float*)d_in[1];
    const float* bq    = (const float*)d_in[2];
    const float* Wk    = (const float*)d_in[3];
    const float* bk    = (const float*)d_in[4];
    const float* Wv    = (const float*)d_in[5];
    const float* bv    = (const float*)d_in[6];
    const float* gamma = (const float*)d_in[7];
    float* out = (float*)d_out;

    qkv_kernel<<<dim3(L / 32, B), 256>>>(x, Wq, bq, Wk, bk, Wv, bv);
    attn_kernel<<<dim3(L / 64, B), 256>>>(x, gamma, out);
}

// round 2
// speedup vs baseline: 1.0000x; 1.0000x over previous
#include <cuda_runtime.h>

#define B 8
#define C 256
#define L 2048
#define D 32

// Scratch (device globals — no cudaMalloc allowed)
__device__ float g_Q[B * L * D];   // [b][l][d]   2 MB
__device__ float g_K[B * L * D];   // [b][l][d]   2 MB
__device__ float g_V[B * L * C];   // [b][l][c]  16 MB

// ---------------------------------------------------------------------------
// packed fp32x2 math (FFMA2 / FMUL2 — only reachable via PTX on sm_103a)
// ---------------------------------------------------------------------------
union F2U { float2 f; unsigned long long u; };

__device__ __forceinline__ float2 ffma2(float2 a, float2 b, float2 c) {
    F2U A, Bv, Cv, Dv;
    A.f = a; Bv.f = b; Cv.f = c;
    asm("fma.rn.f32x2 %0, %1, %2, %3;" : "=l"(Dv.u) : "l"(A.u), "l"(Bv.u), "l"(Cv.u));
    return Dv.f;
}

__device__ __forceinline__ float2 fmul2(float2 a, float2 b) {
    F2U A, Bv, Dv;
    A.f = a; Bv.f = b;
    asm("mul.rn.f32x2 %0, %1, %2;" : "=l"(Dv.u) : "l"(A.u), "l"(Bv.u));
    return Dv.f;
}

// ---------------------------------------------------------------------------
// Kernel 1: QKV projection (1x1 conv == per-position matmul)
// grid (L/32, B), 256 threads. Block handles 32 positions x 320 output rows.
// ---------------------------------------------------------------------------
__global__ __launch_bounds__(256) void qkv_kernel(
    const float* __restrict__ x,
    const float* __restrict__ Wq, const float* __restrict__ bq,
    const float* __restrict__ Wk, const float* __restrict__ bk,
    const float* __restrict__ Wv, const float* __restrict__ bv)
{
    __shared__ float xs[32][260];   // [l][c], pad 260 -> conflict-free float4 reads

    const int b  = blockIdx.y;
    const int l0 = blockIdx.x * 32;
    const int t  = threadIdx.x;

    const float* xb = x + (size_t)b * C * L;
    // load x tile: consecutive threads -> consecutive l (coalesced gmem)
    for (int idx = t; idx < C * 32; idx += 256) {
        int c  = idx >> 5;
        int ll = idx & 31;
        xs[ll][c] = xb[(size_t)c * L + l0 + ll];
    }
    __syncthreads();

    const int w    = t >> 5;    // warp id: output-row group
    const int lane = t & 31;    // position within tile
    const float4* xp = reinterpret_cast<const float4*>(&xs[lane][0]);

    for (int it = 0; it < 40; ++it) {
        int row = it * 8 + w;   // uniform per warp
        const float* Wrow;
        float bias;
        float* dst;
        if (row < 32) {
            Wrow = Wq + row * C; bias = __ldg(&bq[row]);
            dst = &g_Q[((size_t)b * L + l0 + lane) * D + row];
        } else if (row < 64) {
            int d = row - 32;
            Wrow = Wk + d * C; bias = __ldg(&bk[d]);
            dst = &g_K[((size_t)b * L + l0 + lane) * D + d];
        } else {
            int o = row - 64;
            Wrow = Wv + o * C; bias = __ldg(&bv[o]);
            dst = &g_V[((size_t)b * L + l0 + lane) * C + o];
        }
        const float4* wp = reinterpret_cast<const float4*>(Wrow);
        float2 acc = make_float2(0.f, 0.f);
        #pragma unroll 16
        for (int c4 = 0; c4 < 64; ++c4) {
            float4 wv = __ldg(wp + c4);
            float4 xv = xp[c4];
            acc = ffma2(make_float2(wv.x, wv.y), make_float2(xv.x, xv.y), acc);
            acc = ffma2(make_float2(wv.z, wv.w), make_float2(xv.z, xv.w), acc);
        }
        *dst = acc.x + acc.y + bias;
    }
}

// ---------------------------------------------------------------------------
// Kernel 2: flash-style attention + fused epilogue (gamma*out + x)
// grid (L/64, B), 256 threads. Block: 64 queries x 256 channels.
// Thread owns (query i = t&63, channel group g = t>>6 -> 64 channels).
// ---------------------------------------------------------------------------
__global__ __launch_bounds__(256, 2) void attn_kernel(
    const float* __restrict__ x,
    const float* __restrict__ gamma,
    float* __restrict__ out)
{
    __shared__ float Ks[32][33];      // key chunk [j][d]
    __shared__ float Vs[32][256];     // value chunk [j][c]
    __shared__ float Ps[64][33];      // scores/probs [i][j]
    __shared__ float sm[64], sl[64], scorr[64];

    const int b  = blockIdx.y;
    const int i0 = blockIdx.x * 64;
    const int t  = threadIdx.x;
    const int i  = t & 63;
    const int g  = t >> 6;
    const int cbase = g * 64;

    // Q row for this thread's query: 32 floats, loaded once
    float4 qreg[8];
    {
        const float4* qp = reinterpret_cast<const float4*>(&g_Q[((size_t)b * L + i0 + i) * D]);
        #pragma unroll
        for (int k = 0; k < 8; ++k) qreg[k] = __ldg(qp + k);
    }

    if (t < 64) { sm[t] = -1e30f; sl[t] = 0.f; }

    float2 acc[32];
    #pragma unroll
    for (int k = 0; k < 32; ++k) acc[k] = make_float2(0.f, 0.f);

    const float scale = 0.17677669529663687f;  // 1/sqrt(32)
    const float* Kb = &g_K[(size_t)b * L * D];
    const float* Vb = &g_V[(size_t)b * L * C];

    for (int j0 = 0; j0 < L; j0 += 32) {
        __syncthreads();
        // load K chunk
        for (int idx = t; idx < 32 * 32; idx += 256) {
            int j = idx >> 5, d = idx & 31;
            Ks[j][d] = Kb[(size_t)(j0 + j) * D + d];
        }
        // load V chunk (float4, coalesced)
        {
            const float4* vsrc = reinterpret_cast<const float4*>(Vb + (size_t)j0 * C);
            float4* vdst = reinterpret_cast<float4*>(&Vs[0][0]);
            for (int idx = t; idx < 32 * 64; idx += 256) vdst[idx] = vsrc[idx];
        }
        __syncthreads();

        // S = Q K^T * scale : thread computes 8 j's for its query i
        {
            const int jb = g * 8;
            #pragma unroll
            for (int jj = 0; jj < 8; ++jj) {
                int j = jb + jj;
                const float4* kp = reinterpret_cast<const float4*>(&Ks[j][0]);
                float2 a2 = make_float2(0.f, 0.f);
                #pragma unroll
                for (int k = 0; k < 8; ++k) {
                    float4 kv = kp[k];
                    a2 = ffma2(make_float2(qreg[k].x, qreg[k].y), make_float2(kv.x, kv.y), a2);
                    a2 = ffma2(make_float2(qreg[k].z, qreg[k].w), make_float2(kv.z, kv.w), a2);
                }
                Ps[i][j] = (a2.x + a2.y) * scale;
            }
        }
        __syncthreads();

        // online softmax per query (threads 0..63)
        if (t < 64) {
            float mold = sm[t];
            float cmax = mold;
            #pragma unroll
            for (int j = 0; j < 32; ++j) cmax = fmaxf(cmax, Ps[t][j]);
            float corr = __expf(mold - cmax);
            float s = 0.f;
            #pragma unroll
            for (int j = 0; j < 32; ++j) {
                float p = __expf(Ps[t][j] - cmax);
                Ps[t][j] = p;
                s += p;
            }
            sm[t] = cmax;
            sl[t] = sl[t] * corr + s;
            scorr[t] = corr;
        }
        __syncthreads();

        // O update: rescale accumulators, accumulate P * V
        {
            float corr = scorr[i];
            float2 c2 = make_float2(corr, corr);
            #pragma unroll
            for (int k = 0; k < 32; ++k) acc[k] = fmul2(acc[k], c2);

            #pragma unroll 4
            for (int j = 0; j < 32; ++j) {
                float p = Ps[i][j];
                float2 p2 = make_float2(p, p);
                const float4* vrow = reinterpret_cast<const float4*>(&Vs[j][cbase]);
                #pragma unroll
                for (int k = 0; k < 16; ++k) {
                    float4 v = vrow[k];
                    acc[2 * k]     = ffma2(p2, make_float2(v.x, v.y), acc[2 * k]);
                    acc[2 * k + 1] = ffma2(p2, make_float2(v.z, v.w), acc[2 * k + 1]);
                }
            }
        }
    }

    // epilogue: out = gamma * (O / l) + x   (coalesced over i)
    const float linv = 1.f / sl[i];
    const float gam  = __ldg(gamma);
    float* ob       = out + (size_t)b * C * L;
    const float* xb = x   + (size_t)b * C * L;
    #pragma unroll
    for (int k = 0; k < 32; ++k) {
        int c0 = cbase + 2 * k;
        float o0 = gam * (acc[k].x * linv) + xb[(size_t)c0 * L + i0 + i];
        float o1 = gam * (acc[k].y * linv) + xb[(size_t)(c0 + 1) * L + i0 + i];
        ob[(size_t)c0 * L + i0 + i]       = o0;
        ob[(size_t)(c0 + 1) * L + i0 + i] = o1;
    }
}

// ---------------------------------------------------------------------------
extern "C" void kernel_launch(void* const* d_in, const int* in_sizes, int n_in,
                              void* d_out, int out_size)
{
    const float* x     = (const float*)d_in[0];
    const float* Wq    = (const float*)d_in[1];
    const float* bq    = (const float*)d_in[2];
    const float* Wk    = (const float*)d_in[3];
    const float* bk    = (const float*)d_in[4];
    const float* Wv    = (const float*)d_in[5];
    const float* bv    = (const float*)d_in[6];
    const float* gamma = (const float*)d_in[7];
    float* out = (float*)d_out;

    qkv_kernel<<<dim3(L / 32, B), 256>>>(x, Wq, bq, Wk, bk, Wv, bv);
    attn_kernel<<<dim3(L / 64, B), 256>>>(x, gamma, out);
}

// round 4
// speedup vs baseline: 4.8047x; 4.8046x over previous
#include <cuda_runtime.h>
#include <cuda_bf16.h>
#include <cstdint>

#define Bn 8
#define Cn 256
#define Ln 2048
#define Dn 32

// scratch (device globals; no cudaMalloc allowed)
__device__ __nv_bfloat16 g_Qb[Bn * Ln * Dn];   // [b][l][d]  pre-scaled by scale*log2e
__device__ __nv_bfloat16 g_Kb[Bn * Ln * Dn];   // [b][l][d]
__device__ __nv_bfloat16 g_Vb[Bn * Cn * Ln];   // [b][c][l]

// ============================ helpers ======================================
__device__ __forceinline__ uint32_t smem_to_u32(const void* p) {
    uint32_t a;
    asm("{ .reg .u64 t; cvta.to.shared.u64 t, %1; cvt.u32.u64 %0, t; }" : "=r"(a) : "l"(p));
    return a;
}
__device__ __forceinline__ float ex2f(float x) {
    float r; asm("ex2.approx.ftz.f32 %0, %1;" : "=f"(r) : "f"(x)); return r;
}
// res = {lo: a, hi: b} packed bf16x2
#define CVT_BF16X2(res, a, b) \
    asm("cvt.rn.bf16x2.f32 %0, %1, %2;" : "=r"(res) : "f"(b), "f"(a))

__device__ __forceinline__ void ldmatrix_x4(uint32_t& r0, uint32_t& r1, uint32_t& r2, uint32_t& r3, uint32_t addr) {
    asm volatile("ldmatrix.sync.aligned.m8n8.x4.shared.b16 {%0,%1,%2,%3}, [%4];"
                 : "=r"(r0), "=r"(r1), "=r"(r2), "=r"(r3) : "r"(addr));
}
__device__ __forceinline__ void ldmatrix_x2(uint32_t& r0, uint32_t& r1, uint32_t addr) {
    asm volatile("ldmatrix.sync.aligned.m8n8.x2.shared.b16 {%0,%1}, [%2];"
                 : "=r"(r0), "=r"(r1) : "r"(addr));
}
__device__ __forceinline__ void mma_bf16(float& c0, float& c1, float& c2, float& c3,
                                         uint32_t a0, uint32_t a1, uint32_t a2, uint32_t a3,
                                         uint32_t b0, uint32_t b1) {
    asm volatile("mma.sync.aligned.m16n8k16.row.col.f32.bf16.bf16.f32 "
                 "{%0,%1,%2,%3}, {%4,%5,%6,%7}, {%8,%9}, {%0,%1,%2,%3};"
                 : "+f"(c0), "+f"(c1), "+f"(c2), "+f"(c3)
                 : "r"(a0), "r"(a1), "r"(a2), "r"(a3), "r"(b0), "r"(b1));
}

// f32x2 packed FMA (QKV kernel)
union F2U { float2 f; unsigned long long u; };
__device__ __forceinline__ float2 ffma2(float2 a, float2 b, float2 c) {
    F2U A, Bv, Cv, Dv; A.f = a; Bv.f = b; Cv.f = c;
    asm("fma.rn.f32x2 %0, %1, %2, %3;" : "=l"(Dv.u) : "l"(A.u), "l"(Bv.u), "l"(Cv.u));
    return Dv.f;
}
// expand packed bf16x2 -> float2 (lo = even channel)
__device__ __forceinline__ float2 bf2f2(uint32_t u) {
    F2U e;
    e.u = ((unsigned long long)(u & 0xFFFF0000u) << 32) | ((unsigned long long)(u << 16));
    return e.f;
}

// ===========================================================================
// Kernel 1: QKV projection -> bf16 scratch. grid (L/64, B), 256 threads.
// x tile staged as bf16x2 pairs; 8 rows x 2 positions per thread.
// ===========================================================================
__global__ __launch_bounds__(256) void qkv_kernel(
    const float* __restrict__ x,
    const float* __restrict__ Wq, const float* __restrict__ bq,
    const float* __restrict__ Wk, const float* __restrict__ bk,
    const float* __restrict__ Wv, const float* __restrict__ bv)
{
    __shared__ uint32_t xs[64 * 132];   // [l][128 bf16x2 pairs], pad 132
    const int b = blockIdx.y, l0 = blockIdx.x * 64, t = threadIdx.x;
    const float* xb = x + (size_t)b * Cn * Ln;

    for (int idx = t; idx < 128 * 64; idx += 256) {
        int cp = idx >> 6, ll = idx & 63;
        float f0 = xb[(size_t)(2 * cp) * Ln + l0 + ll];
        float f1 = xb[(size_t)(2 * cp + 1) * Ln + l0 + ll];
        uint32_t p; CVT_BF16X2(p, f0, f1);
        xs[ll * 132 + cp] = p;
    }
    __syncthreads();

    const int w = t >> 5, lane = t & 31;
    const uint32_t* x0 = &xs[lane * 132];
    const uint32_t* x1 = &xs[(lane + 32) * 132];
    const float qs = 1.4426950408889634f * 0.17677669529663687f;  // log2e / sqrt(D)

    for (int it = 0; it < 5; ++it) {
        const int rbase = it * 64 + w * 8;
        const float* wrow[8]; float bias[8];
        #pragma unroll
        for (int rr = 0; rr < 8; ++rr) {
            int row = rbase + rr;
            if (row < 32)      { wrow[rr] = Wq + row * Cn;        bias[rr] = bq[row]; }
            else if (row < 64) { wrow[rr] = Wk + (row - 32) * Cn; bias[rr] = bk[row - 32]; }
            else               { wrow[rr] = Wv + (row - 64) * Cn; bias[rr] = bv[row - 64]; }
        }
        float2 acc[16];
        #pragma unroll
        for (int k = 0; k < 16; ++k) acc[k] = make_float2(0.f, 0.f);

        #pragma unroll 4
        for (int c2 = 0; c2 < 64; ++c2) {
            uint2 u0 = *reinterpret_cast<const uint2*>(&x0[c2 * 2]);
            uint2 u1 = *reinterpret_cast<const uint2*>(&x1[c2 * 2]);
            float2 xa0 = bf2f2(u0.x), xb0 = bf2f2(u0.y);
            float2 xa1 = bf2f2(u1.x), xb1 = bf2f2(u1.y);
            #pragma unroll
            for (int rr = 0; rr < 8; ++rr) {
                float4 wv = __ldg(reinterpret_cast<const float4*>(wrow[rr]) + c2);
                float2 wlo = make_float2(wv.x, wv.y), whi = make_float2(wv.z, wv.w);
                acc[rr * 2]     = ffma2(wlo, xa0, acc[rr * 2]);
                acc[rr * 2]     = ffma2(whi, xb0, acc[rr * 2]);
                acc[rr * 2 + 1] = ffma2(wlo, xa1, acc[rr * 2 + 1]);
                acc[rr * 2 + 1] = ffma2(whi, xb1, acc[rr * 2 + 1]);
            }
        }
        #pragma unroll
        for (int rr = 0; rr < 8; ++rr) {
            int row = rbase + rr;
            float v0 = acc[rr * 2].x + acc[rr * 2].y + bias[rr];
            float v1 = acc[rr * 2 + 1].x + acc[rr * 2 + 1].y + bias[rr];
            if (row < 32) {
                g_Qb[((size_t)b * Ln + l0 + lane) * Dn + row]      = __float2bfloat16(v0 * qs);
                g_Qb[((size_t)b * Ln + l0 + lane + 32) * Dn + row] = __float2bfloat16(v1 * qs);
            } else if (row < 64) {
                int d = row - 32;
                g_Kb[((size_t)b * Ln + l0 + lane) * Dn + d]      = __float2bfloat16(v0);
                g_Kb[((size_t)b * Ln + l0 + lane + 32) * Dn + d] = __float2bfloat16(v1);
            } else {
                int o = row - 64;
                g_Vb[((size_t)b * Cn + o) * Ln + l0 + lane]      = __float2bfloat16(v0);
                g_Vb[((size_t)b * Cn + o) * Ln + l0 + lane + 32] = __float2bfloat16(v1);
            }
        }
    }
}

// ===========================================================================
// Kernel 2: HMMA (mma.sync bf16) flash attention. grid (L/64, B), 256 thr.
// Warp w: rg = w>>1 (16 queries), ch = w&1 (128 channels).
// ===========================================================================
__global__ __launch_bounds__(256, 1) void attn_kernel(
    const float* __restrict__ x,
    const float* __restrict__ gamma,
    float* __restrict__ out)
{
    __shared__ __nv_bfloat16 Qsm[64 * 40];             // [q][d] pitch 40
    __shared__ __nv_bfloat16 Ksm[64 * 40];             // [j][d] pitch 40
    __shared__ __align__(16) char VTsm[256 * 72 * 2];  // V bf16 [c][j] pitch 72 / transpose f32 [128][68]

    const int b = blockIdx.y, i0 = blockIdx.x * 64, t = threadIdx.x;
    const int w = t >> 5, lane = t & 31;
    const int rg = w >> 1, ch = w & 1;

    const uint32_t qsm_u = smem_to_u32(Qsm);
    const uint32_t ksm_u = smem_to_u32(Ksm);
    const uint32_t vsm_u = smem_to_u32(VTsm);
    __nv_bfloat16* Vsm = reinterpret_cast<__nv_bfloat16*>(VTsm);

    const __nv_bfloat16* Qg = &g_Qb[((size_t)b * Ln + i0) * Dn];
    const __nv_bfloat16* Kg = &g_Kb[(size_t)b * Ln * Dn];
    const __nv_bfloat16* Vg = &g_Vb[(size_t)b * Cn * Ln];

    // stage Q tile: 64 q x 32 d  (256 x uint4)
    {
        int q = t >> 2, dc = t & 3;
        uint4 v = *reinterpret_cast<const uint4*>(Qg + (size_t)q * Dn + dc * 8);
        *reinterpret_cast<uint4*>(&Qsm[q * 40 + dc * 8]) = v;
    }
    __syncthreads();

    // Q a-frags (k=0..15, k=16..31), loaded once
    uint32_t aq[2][4];
    {
        uint32_t base = qsm_u + ((rg * 16 + (lane & 15)) * 40 + ((lane >> 4) & 1) * 8) * 2;
        ldmatrix_x4(aq[0][0], aq[0][1], aq[0][2], aq[0][3], base);
        ldmatrix_x4(aq[1][0], aq[1][1], aq[1][2], aq[1][3], base + 32);
    }

    // ldmatrix lane-base offsets (bytes)
    const uint32_t kb_lane = (lane & 7) * 80 + ((lane >> 3) & 1) * 16;          // x2 (t0..15 used)
    const uint32_t vb_lane = (lane & 7) * 144 + (lane >> 3) * 16;               // x4

    float of[16][4];
    #pragma unroll
    for (int n = 0; n < 16; ++n)
        #pragma unroll
        for (int k = 0; k < 4; ++k) of[n][k] = 0.f;
    float lsum0 = 0.f, lsum1 = 0.f;

    for (int j0 = 0; j0 < Ln; j0 += 64) {
        __syncthreads();   // prior chunk's ldmatrix reads done
        // stage K chunk: 64 j x 32 d
        {
            int j = t >> 2, dc = t & 3;
            uint4 v = *reinterpret_cast<const uint4*>(Kg + (size_t)(j0 + j) * Dn + dc * 8);
            *reinterpret_cast<uint4*>(&Ksm[j * 40 + dc * 8]) = v;
        }
        // stage V chunk: 256 c x 64 j (pitch 72)
        for (int idx = t; idx < 256 * 8; idx += 256) {
            int c = idx >> 3, k = idx & 7;
            uint4 v = *reinterpret_cast<const uint4*>(Vg + (size_t)c * Ln + j0 + k * 8);
            *reinterpret_cast<uint4*>(&Vsm[c * 72 + k * 8]) = v;
        }
        __syncthreads();

        // S = Q K^T (16 x 64) -> exp -> P a-frags
        uint32_t pa[4][4];
        #pragma unroll
        for (int jt = 0; jt < 8; ++jt) {
            float s0 = 0.f, s1 = 0.f, s2 = 0.f, s3 = 0.f;
            uint32_t b0, b1;
            uint32_t kaddr = ksm_u + jt * 640 + kb_lane;
            ldmatrix_x2(b0, b1, kaddr);
            mma_bf16(s0, s1, s2, s3, aq[0][0], aq[0][1], aq[0][2], aq[0][3], b0, b1);
            ldmatrix_x2(b0, b1, kaddr + 32);
            mma_bf16(s0, s1, s2, s3, aq[1][0], aq[1][1], aq[1][2], aq[1][3], b0, b1);

            float e0 = ex2f(s0), e1 = ex2f(s1), e2 = ex2f(s2), e3 = ex2f(s3);
            lsum0 += e0 + e1;
            lsum1 += e2 + e3;
            uint32_t plo, phi;
            CVT_BF16X2(plo, e0, e1);
            CVT_BF16X2(phi, e2, e3);
            int pt = jt >> 1;
            if ((jt & 1) == 0) { pa[pt][0] = plo; pa[pt][1] = phi; }
            else               { pa[pt][2] = plo; pa[pt][3] = phi; }
        }

        // O += P V^T : 16 n-tiles (128 channels), k = 64
        #pragma unroll
        for (int nt = 0; nt < 16; ++nt) {
            uint32_t vbase = vsm_u + (uint32_t)(ch * 128 + nt * 8) * 144 + vb_lane;
            uint32_t b0, b1, b2, b3;
            ldmatrix_x4(b0, b1, b2, b3, vbase);
            mma_bf16(of[nt][0], of[nt][1], of[nt][2], of[nt][3],
                     pa[0][0], pa[0][1], pa[0][2], pa[0][3], b0, b1);
            mma_bf16(of[nt][0], of[nt][1], of[nt][2], of[nt][3],
                     pa[1][0], pa[1][1], pa[1][2], pa[1][3], b2, b3);
            ldmatrix_x4(b0, b1, b2, b3, vbase + 64);
            mma_bf16(of[nt][0], of[nt][1], of[nt][2], of[nt][3],
                     pa[2][0], pa[2][1], pa[2][2], pa[2][3], b0, b1);
            mma_bf16(of[nt][0], of[nt][1], of[nt][2], of[nt][3],
                     pa[3][0], pa[3][1], pa[3][2], pa[3][3], b2, b3);
        }
    }

    // row-sum reduction across the quad (lanes sharing lane>>2)
    lsum0 += __shfl_xor_sync(0xFFFFFFFF, lsum0, 1);
    lsum0 += __shfl_xor_sync(0xFFFFFFFF, lsum0, 2);
    lsum1 += __shfl_xor_sync(0xFFFFFFFF, lsum1, 1);
    lsum1 += __shfl_xor_sync(0xFFFFFFFF, lsum1, 2);
    const float linv0 = 1.f / lsum0;
    const float linv1 = 1.f / lsum1;
    const float gam = __ldg(gamma);

    float* Tsm = reinterpret_cast<float*>(VTsm);   // [128][68]
    const float* xb = x + (size_t)b * Cn * Ln;
    float* ob = out + (size_t)b * Cn * Ln;

    for (int h = 0; h < 2; ++h) {
        __syncthreads();
        if (ch == h) {
            int q = rg * 16 + (lane >> 2);
            #pragma unroll
            for (int nt = 0; nt < 16; ++nt) {
                int cl = nt * 8 + (lane & 3) * 2;
                Tsm[cl * 68 + q]           = of[nt][0] * linv0;
                Tsm[(cl + 1) * 68 + q]     = of[nt][1] * linv0;
                Tsm[cl * 68 + q + 8]       = of[nt][2] * linv1;
                Tsm[(cl + 1) * 68 + q + 8] = of[nt][3] * linv1;
            }
        }
        __syncthreads();
        for (int idx = t; idx < 128 * 64; idx += 256) {
            int cl = idx >> 6, q = idx & 63;
            size_t off = (size_t)(h * 128 + cl) * Ln + i0 + q;
            ob[off] = gam * Tsm[cl * 68 + q] + xb[off];
        }
    }
}

// ===========================================================================
extern "C" void kernel_launch(void* const* d_in, const int* in_sizes, int n_in,
                              void* d_out, int out_size)
{
    const float* x     = (const float*)d_in[0];
    const float* Wq    = (const float*)d_in[1];
    const float* bq    = (const float*)d_in[2];
    const float* Wk    = (const float*)d_in[3];
    const float* bk    = (const float*)d_in[4];
    const float* Wv    = (const float*)d_in[5];
    const float* bv    = (const float*)d_in[6];
    const float* gamma = (const float*)d_in[7];
    float* out = (float*)d_out;

    qkv_kernel<<<dim3(Ln / 64, Bn), 256>>>(x, Wq, bq, Wk, bk, Wv, bv);
    attn_kernel<<<dim3(Ln / 64, Bn), 256>>>(x, gamma, out);
}

// round 5
// speedup vs baseline: 5.5865x; 1.1627x over previous
#include <cuda_runtime.h>
#include <cuda_bf16.h>
#include <cstdint>

#define Bn 8
#define Cn 256
#define Ln 2048
#define Dn 32

// scratch (device globals; no cudaMalloc allowed)
__device__ __nv_bfloat16 g_Qb[Bn * Ln * Dn];   // [b][l][d]  pre-scaled by scale*log2e
__device__ __nv_bfloat16 g_Kb[Bn * Ln * Dn];   // [b][l][d]
__device__ __nv_bfloat16 g_Vb[Bn * Cn * Ln];   // [b][c][l]

// ============================ helpers ======================================
__device__ __forceinline__ uint32_t smem_to_u32(const void* p) {
    uint32_t a;
    asm("{ .reg .u64 t; cvta.to.shared.u64 t, %1; cvt.u32.u64 %0, t; }" : "=r"(a) : "l"(p));
    return a;
}
__device__ __forceinline__ float ex2f(float x) {
    float r; asm("ex2.approx.ftz.f32 %0, %1;" : "=f"(r) : "f"(x)); return r;
}
#define CVT_BF16X2(res, a, b) \
    asm("cvt.rn.bf16x2.f32 %0, %1, %2;" : "=r"(res) : "f"(b), "f"(a))

__device__ __forceinline__ void ldmatrix_x4(uint32_t& r0, uint32_t& r1, uint32_t& r2, uint32_t& r3, uint32_t addr) {
    asm volatile("ldmatrix.sync.aligned.m8n8.x4.shared.b16 {%0,%1,%2,%3}, [%4];"
                 : "=r"(r0), "=r"(r1), "=r"(r2), "=r"(r3) : "r"(addr));
}
__device__ __forceinline__ void ldmatrix_x2(uint32_t& r0, uint32_t& r1, uint32_t addr) {
    asm volatile("ldmatrix.sync.aligned.m8n8.x2.shared.b16 {%0,%1}, [%2];"
                 : "=r"(r0), "=r"(r1) : "r"(addr));
}
__device__ __forceinline__ void mma_bf16(float& c0, float& c1, float& c2, float& c3,
                                         uint32_t a0, uint32_t a1, uint32_t a2, uint32_t a3,
                                         uint32_t b0, uint32_t b1) {
    asm volatile("mma.sync.aligned.m16n8k16.row.col.f32.bf16.bf16.f32 "
                 "{%0,%1,%2,%3}, {%4,%5,%6,%7}, {%8,%9}, {%0,%1,%2,%3};"
                 : "+f"(c0), "+f"(c1), "+f"(c2), "+f"(c3)
                 : "r"(a0), "r"(a1), "r"(a2), "r"(a3), "r"(b0), "r"(b1));
}
__device__ __forceinline__ void cp_async16(uint32_t saddr, const void* gptr) {
    asm volatile("cp.async.cg.shared.global [%0], [%1], 16;" :: "r"(saddr), "l"(gptr));
}
#define CP_COMMIT() asm volatile("cp.async.commit_group;" ::: "memory")
#define CP_WAIT0()  asm volatile("cp.async.wait_group 0;" ::: "memory")

// f32x2 packed FMA (QKV kernel)
union F2U { float2 f; unsigned long long u; };
__device__ __forceinline__ float2 ffma2(float2 a, float2 b, float2 c) {
    F2U A, Bv, Cv, Dv; A.f = a; Bv.f = b; Cv.f = c;
    asm("fma.rn.f32x2 %0, %1, %2, %3;" : "=l"(Dv.u) : "l"(A.u), "l"(Bv.u), "l"(Cv.u));
    return Dv.f;
}
__device__ __forceinline__ float2 bf2f2(uint32_t u) {
    F2U e;
    e.u = ((unsigned long long)(u & 0xFFFF0000u) << 32) | ((unsigned long long)(u << 16));
    return e.f;
}

// ===========================================================================
// Kernel 1: QKV projection -> bf16 scratch. grid (L/64, B), 256 threads.
// ===========================================================================
__global__ __launch_bounds__(256) void qkv_kernel(
    const float* __restrict__ x,
    const float* __restrict__ Wq, const float* __restrict__ bq,
    const float* __restrict__ Wk, const float* __restrict__ bk,
    const float* __restrict__ Wv, const float* __restrict__ bv)
{
    __shared__ uint32_t xs[64 * 132];   // [l][128 bf16x2 pairs], pad 132
    const int b = blockIdx.y, l0 = blockIdx.x * 64, t = threadIdx.x;
    const float* xb = x + (size_t)b * Cn * Ln;

    for (int idx = t; idx < 128 * 64; idx += 256) {
        int cp = idx >> 6, ll = idx & 63;
        float f0 = xb[(size_t)(2 * cp) * Ln + l0 + ll];
        float f1 = xb[(size_t)(2 * cp + 1) * Ln + l0 + ll];
        uint32_t p; CVT_BF16X2(p, f0, f1);
        xs[ll * 132 + cp] = p;
    }
    __syncthreads();

    const int w = t >> 5, lane = t & 31;
    const uint32_t* x0 = &xs[lane * 132];
    const uint32_t* x1 = &xs[(lane + 32) * 132];
    const float qs = 1.4426950408889634f * 0.17677669529663687f;  // log2e / sqrt(D)

    for (int it = 0; it < 5; ++it) {
        const int rbase = it * 64 + w * 8;
        const float* wrow[8]; float bias[8];
        #pragma unroll
        for (int rr = 0; rr < 8; ++rr) {
            int row = rbase + rr;
            if (row < 32)      { wrow[rr] = Wq + row * Cn;        bias[rr] = bq[row]; }
            else if (row < 64) { wrow[rr] = Wk + (row - 32) * Cn; bias[rr] = bk[row - 32]; }
            else               { wrow[rr] = Wv + (row - 64) * Cn; bias[rr] = bv[row - 64]; }
        }
        float2 acc[16];
        #pragma unroll
        for (int k = 0; k < 16; ++k) acc[k] = make_float2(0.f, 0.f);

        #pragma unroll 4
        for (int c2 = 0; c2 < 64; ++c2) {
            uint2 u0 = *reinterpret_cast<const uint2*>(&x0[c2 * 2]);
            uint2 u1 = *reinterpret_cast<const uint2*>(&x1[c2 * 2]);
            float2 xa0 = bf2f2(u0.x), xb0 = bf2f2(u0.y);
            float2 xa1 = bf2f2(u1.x), xb1 = bf2f2(u1.y);
            #pragma unroll
            for (int rr = 0; rr < 8; ++rr) {
                float4 wv = __ldg(reinterpret_cast<const float4*>(wrow[rr]) + c2);
                float2 wlo = make_float2(wv.x, wv.y), whi = make_float2(wv.z, wv.w);
                acc[rr * 2]     = ffma2(wlo, xa0, acc[rr * 2]);
                acc[rr * 2]     = ffma2(whi, xb0, acc[rr * 2]);
                acc[rr * 2 + 1] = ffma2(wlo, xa1, acc[rr * 2 + 1]);
                acc[rr * 2 + 1] = ffma2(whi, xb1, acc[rr * 2 + 1]);
            }
        }
        #pragma unroll
        for (int rr = 0; rr < 8; ++rr) {
            int row = rbase + rr;
            float v0 = acc[rr * 2].x + acc[rr * 2].y + bias[rr];
            float v1 = acc[rr * 2 + 1].x + acc[rr * 2 + 1].y + bias[rr];
            if (row < 32) {
                g_Qb[((size_t)b * Ln + l0 + lane) * Dn + row]      = __float2bfloat16(v0 * qs);
                g_Qb[((size_t)b * Ln + l0 + lane + 32) * Dn + row] = __float2bfloat16(v1 * qs);
            } else if (row < 64) {
                int d = row - 32;
                g_Kb[((size_t)b * Ln + l0 + lane) * Dn + d]      = __float2bfloat16(v0);
                g_Kb[((size_t)b * Ln + l0 + lane + 32) * Dn + d] = __float2bfloat16(v1);
            } else {
                int o = row - 64;
                g_Vb[((size_t)b * Cn + o) * Ln + l0 + lane]      = __float2bfloat16(v0);
                g_Vb[((size_t)b * Cn + o) * Ln + l0 + lane + 32] = __float2bfloat16(v1);
            }
        }
    }
}

// ===========================================================================
// Kernel 2: HMMA flash attention, cp.async double-buffered.
// grid (L/64, B), 256 threads. Warp w: rg=w>>1 (16 q), ch=w&1 (128 ch).
// Dynamic smem layout (bytes):
//   [0, 5120)        Q   [64][40] bf16
//   [5120 + bi*5120) K   [2][64][40] bf16
//   [15360 + bi*36864) V [2][256][72] bf16   (buffer 0 reused as f32 [128][68])
// ===========================================================================
#define SM_Q  0
#define SM_K(bi) (5120 + (bi) * 5120)
#define SM_V(bi) (15360 + (bi) * 36864)
#define SM_TOTAL (15360 + 2 * 36864)

__global__ __launch_bounds__(256, 1) void attn_kernel(
    const float* __restrict__ x,
    const float* __restrict__ gamma,
    float* __restrict__ out)
{
    extern __shared__ __align__(16) char dsm[];
    const int b = blockIdx.y, i0 = blockIdx.x * 64, t = threadIdx.x;
    const int w = t >> 5, lane = t & 31;
    const int rg = w >> 1, ch = w & 1;

    const uint32_t sbase = smem_to_u32(dsm);
    __nv_bfloat16* Qsm = reinterpret_cast<__nv_bfloat16*>(dsm + SM_Q);

    const __nv_bfloat16* Qg = &g_Qb[((size_t)b * Ln + i0) * Dn];
    const __nv_bfloat16* Kg = &g_Kb[(size_t)b * Ln * Dn];
    const __nv_bfloat16* Vg = &g_Vb[(size_t)b * Cn * Ln];

    // stage Q tile: 64 q x 32 d
    {
        int q = t >> 2, dc = t & 3;
        uint4 v = *reinterpret_cast<const uint4*>(Qg + (size_t)q * Dn + dc * 8);
        *reinterpret_cast<uint4*>(&Qsm[q * 40 + dc * 8]) = v;
    }

    // prologue: issue chunk 0 loads (K: 1 op/thread, V: 8 ops/thread)
    {
        int j = t >> 2, dc = t & 3;
        cp_async16(sbase + SM_K(0) + (j * 40 + dc * 8) * 2, Kg + (size_t)j * Dn + dc * 8);
        int c = t >> 3, k = t & 7;
        #pragma unroll
        for (int cc = 0; cc < 8; ++cc)
            cp_async16(sbase + SM_V(0) + ((c + cc * 32) * 72 + k * 8) * 2,
                       Vg + (size_t)(c + cc * 32) * Ln + k * 8);
    }
    CP_COMMIT();
    __syncthreads();

    // Q a-frags (k=0..15, 16..31), loaded once
    uint32_t aq[2][4];
    {
        uint32_t base = sbase + SM_Q + ((rg * 16 + (lane & 15)) * 40 + ((lane >> 4) & 1) * 8) * 2;
        ldmatrix_x4(aq[0][0], aq[0][1], aq[0][2], aq[0][3], base);
        ldmatrix_x4(aq[1][0], aq[1][1], aq[1][2], aq[1][3], base + 32);
    }

    const uint32_t kb_lane = (lane & 7) * 80 + ((lane >> 3) & 1) * 16;
    const uint32_t vb_lane = (lane & 7) * 144 + (lane >> 3) * 16;

    float of[16][4];
    #pragma unroll
    for (int n = 0; n < 16; ++n)
        #pragma unroll
        for (int k = 0; k < 4; ++k) of[n][k] = 0.f;
    float lsum0 = 0.f, lsum1 = 0.f;

    for (int cidx = 0; cidx < Ln / 64; ++cidx) {
        CP_WAIT0();
        __syncthreads();   // chunk cidx data visible; all warps done reading buf[cidx^1]

        // issue chunk cidx+1 into the other buffer (overlaps compute below)
        if (cidx + 1 < Ln / 64) {
            int j0n = (cidx + 1) * 64;
            int bi = (cidx + 1) & 1;
            int j = t >> 2, dc = t & 3;
            cp_async16(sbase + SM_K(bi) + (j * 40 + dc * 8) * 2,
                       Kg + (size_t)(j0n + j) * Dn + dc * 8);
            int c = t >> 3, k = t & 7;
            #pragma unroll
            for (int cc = 0; cc < 8; ++cc)
                cp_async16(sbase + SM_V(bi) + ((c + cc * 32) * 72 + k * 8) * 2,
                           Vg + (size_t)(c + cc * 32) * Ln + j0n + k * 8);
        }
        CP_COMMIT();

        const uint32_t ks_u = sbase + SM_K(cidx & 1);
        const uint32_t vs_u = sbase + SM_V(cidx & 1);

        // S = Q K^T (16 x 64) -> exp -> P a-frags
        uint32_t pa[4][4];
        #pragma unroll
        for (int jt = 0; jt < 8; ++jt) {
            float s0 = 0.f, s1 = 0.f, s2 = 0.f, s3 = 0.f;
            uint32_t b0, b1;
            uint32_t kaddr = ks_u + jt * 640 + kb_lane;
            ldmatrix_x2(b0, b1, kaddr);
            mma_bf16(s0, s1, s2, s3, aq[0][0], aq[0][1], aq[0][2], aq[0][3], b0, b1);
            ldmatrix_x2(b0, b1, kaddr + 32);
            mma_bf16(s0, s1, s2, s3, aq[1][0], aq[1][1], aq[1][2], aq[1][3], b0, b1);

            float e0 = ex2f(s0), e1 = ex2f(s1), e2 = ex2f(s2), e3 = ex2f(s3);
            lsum0 += e0 + e1;
            lsum1 += e2 + e3;
            uint32_t plo, phi;
            CVT_BF16X2(plo, e0, e1);
            CVT_BF16X2(phi, e2, e3);
            int pt = jt >> 1;
            if ((jt & 1) == 0) { pa[pt][0] = plo; pa[pt][1] = phi; }
            else               { pa[pt][2] = plo; pa[pt][3] = phi; }
        }

        // O += P V^T : 16 n-tiles (128 channels), k = 64
        #pragma unroll
        for (int nt = 0; nt < 16; ++nt) {
            uint32_t vbase = vs_u + (uint32_t)(ch * 128 + nt * 8) * 144 + vb_lane;
            uint32_t b0, b1, b2, b3;
            ldmatrix_x4(b0, b1, b2, b3, vbase);
            mma_bf16(of[nt][0], of[nt][1], of[nt][2], of[nt][3],
                     pa[0][0], pa[0][1], pa[0][2], pa[0][3], b0, b1);
            mma_bf16(of[nt][0], of[nt][1], of[nt][2], of[nt][3],
                     pa[1][0], pa[1][1], pa[1][2], pa[1][3], b2, b3);
            ldmatrix_x4(b0, b1, b2, b3, vbase + 64);
            mma_bf16(of[nt][0], of[nt][1], of[nt][2], of[nt][3],
                     pa[2][0], pa[2][1], pa[2][2], pa[2][3], b0, b1);
            mma_bf16(of[nt][0], of[nt][1], of[nt][2], of[nt][3],
                     pa[3][0], pa[3][1], pa[3][2], pa[3][3], b2, b3);
        }
    }

    // row-sum reduction across the quad
    lsum0 += __shfl_xor_sync(0xFFFFFFFF, lsum0, 1);
    lsum0 += __shfl_xor_sync(0xFFFFFFFF, lsum0, 2);
    lsum1 += __shfl_xor_sync(0xFFFFFFFF, lsum1, 1);
    lsum1 += __shfl_xor_sync(0xFFFFFFFF, lsum1, 2);
    const float linv0 = 1.f / lsum0;
    const float linv1 = 1.f / lsum1;
    const float gam = __ldg(gamma);

    float* Tsm = reinterpret_cast<float*>(dsm + SM_V(0));   // [128][68] f32
    const float* xb = x + (size_t)b * Cn * Ln;
    float* ob = out + (size_t)b * Cn * Ln;

    for (int h = 0; h < 2; ++h) {
        __syncthreads();
        if (ch == h) {
            int q = rg * 16 + (lane >> 2);
            #pragma unroll
            for (int nt = 0; nt < 16; ++nt) {
                int cl = nt * 8 + (lane & 3) * 2;
                Tsm[cl * 68 + q]           = of[nt][0] * linv0;
                Tsm[(cl + 1) * 68 + q]     = of[nt][1] * linv0;
                Tsm[cl * 68 + q + 8]       = of[nt][2] * linv1;
                Tsm[(cl + 1) * 68 + q + 8] = of[nt][3] * linv1;
            }
        }
        __syncthreads();
        for (int idx = t; idx < 128 * 64; idx += 256) {
            int cl = idx >> 6, q = idx & 63;
            size_t off = (size_t)(h * 128 + cl) * Ln + i0 + q;
            ob[off] = gam * Tsm[cl * 68 + q] + xb[off];
        }
    }
}

// ===========================================================================
extern "C" void kernel_launch(void* const* d_in, const int* in_sizes, int n_in,
                              void* d_out, int out_size)
{
    const float* x     = (const float*)d_in[0];
    const float* Wq    = (const float*)d_in[1];
    const float* bq    = (const float*)d_in[2];
    const float* Wk    = (const float*)d_in[3];
    const float* bk    = (const float*)d_in[4];
    const float* Wv    = (const float*)d_in[5];
    const float* bv    = (const float*)d_in[6];
    const float* gamma = (const float*)d_in[7];
    float* out = (float*)d_out;

    cudaFuncSetAttribute(attn_kernel, cudaFuncAttributeMaxDynamicSharedMemorySize, SM_TOTAL);

    qkv_kernel<<<dim3(Ln / 64, Bn), 256>>>(x, Wq, bq, Wk, bk, Wv, bv);
    attn_kernel<<<dim3(Ln / 64, Bn), 256, SM_TOTAL>>>(x, gamma, out);
}

// round 6
// speedup vs baseline: 5.7149x; 1.0230x over previous
#include <cuda_runtime.h>
#include <cuda_bf16.h>
#include <cstdint>

#define Bn 8
#define Cn 256
#define Ln 2048
#define Dn 32

// scratch (device globals; no cudaMalloc allowed)
__device__ __nv_bfloat16 g_Qb[Bn * Ln * Dn];   // [b][l][d]  pre-scaled by scale*log2e
__device__ __nv_bfloat16 g_Kb[Bn * Ln * Dn];   // [b][l][d]
__device__ __nv_bfloat16 g_Vb[Bn * Cn * Ln];   // [b][c][l]

// ============================ helpers ======================================
__device__ __forceinline__ uint32_t smem_to_u32(const void* p) {
    uint32_t a;
    asm("{ .reg .u64 t; cvta.to.shared.u64 t, %1; cvt.u32.u64 %0, t; }" : "=r"(a) : "l"(p));
    return a;
}
__device__ __forceinline__ float ex2f(float x) {
    float r; asm("ex2.approx.ftz.f32 %0, %1;" : "=f"(r) : "f"(x)); return r;
}
#define CVT_BF16X2(res, a, b) \
    asm("cvt.rn.bf16x2.f32 %0, %1, %2;" : "=r"(res) : "f"(b), "f"(a))

__device__ __forceinline__ void ldmatrix_x4(uint32_t& r0, uint32_t& r1, uint32_t& r2, uint32_t& r3, uint32_t addr) {
    asm volatile("ldmatrix.sync.aligned.m8n8.x4.shared.b16 {%0,%1,%2,%3}, [%4];"
                 : "=r"(r0), "=r"(r1), "=r"(r2), "=r"(r3) : "r"(addr));
}
__device__ __forceinline__ void ldmatrix_x2(uint32_t& r0, uint32_t& r1, uint32_t addr) {
    asm volatile("ldmatrix.sync.aligned.m8n8.x2.shared.b16 {%0,%1}, [%2];"
                 : "=r"(r0), "=r"(r1) : "r"(addr));
}
__device__ __forceinline__ void mma_bf16(float& c0, float& c1, float& c2, float& c3,
                                         uint32_t a0, uint32_t a1, uint32_t a2, uint32_t a3,
                                         uint32_t b0, uint32_t b1) {
    asm volatile("mma.sync.aligned.m16n8k16.row.col.f32.bf16.bf16.f32 "
                 "{%0,%1,%2,%3}, {%4,%5,%6,%7}, {%8,%9}, {%0,%1,%2,%3};"
                 : "+f"(c0), "+f"(c1), "+f"(c2), "+f"(c3)
                 : "r"(a0), "r"(a1), "r"(a2), "r"(a3), "r"(b0), "r"(b1));
}
__device__ __forceinline__ void cp_async16(uint32_t saddr, const void* gptr) {
    asm volatile("cp.async.cg.shared.global [%0], [%1], 16;" :: "r"(saddr), "l"(gptr));
}
#define CP_COMMIT() asm volatile("cp.async.commit_group;" ::: "memory")
#define CP_WAIT0()  asm volatile("cp.async.wait_group 0;" ::: "memory")

// f32x2 packed FMA (QKV kernel)
union F2U { float2 f; unsigned long long u; };
__device__ __forceinline__ float2 ffma2(float2 a, float2 b, float2 c) {
    F2U A, Bv, Cv, Dv; A.f = a; Bv.f = b; Cv.f = c;
    asm("fma.rn.f32x2 %0, %1, %2, %3;" : "=l"(Dv.u) : "l"(A.u), "l"(Bv.u), "l"(Cv.u));
    return Dv.f;
}
__device__ __forceinline__ float2 bf2f2(uint32_t u) {
    F2U e;
    e.u = ((unsigned long long)(u & 0xFFFF0000u) << 32) | ((unsigned long long)(u << 16));
    return e.f;
}

// ===========================================================================
// Kernel 1: QKV projection -> bf16 scratch. grid (L/64, B), 256 threads.
// ===========================================================================
__global__ __launch_bounds__(256) void qkv_kernel(
    const float* __restrict__ x,
    const float* __restrict__ Wq, const float* __restrict__ bq,
    const float* __restrict__ Wk, const float* __restrict__ bk,
    const float* __restrict__ Wv, const float* __restrict__ bv)
{
    __shared__ uint32_t xs[64 * 132];   // [l][128 bf16x2 pairs], pad 132
    const int b = blockIdx.y, l0 = blockIdx.x * 64, t = threadIdx.x;
    const float* xb = x + (size_t)b * Cn * Ln;

    for (int idx = t; idx < 128 * 64; idx += 256) {
        int cp = idx >> 6, ll = idx & 63;
        float f0 = xb[(size_t)(2 * cp) * Ln + l0 + ll];
        float f1 = xb[(size_t)(2 * cp + 1) * Ln + l0 + ll];
        uint32_t p; CVT_BF16X2(p, f0, f1);
        xs[ll * 132 + cp] = p;
    }
    __syncthreads();

    const int w = t >> 5, lane = t & 31;
    const uint32_t* x0 = &xs[lane * 132];
    const uint32_t* x1 = &xs[(lane + 32) * 132];
    const float qs = 1.4426950408889634f * 0.17677669529663687f;  // log2e / sqrt(D)

    for (int it = 0; it < 5; ++it) {
        const int rbase = it * 64 + w * 8;
        const float* wrow[8]; float bias[8];
        #pragma unroll
        for (int rr = 0; rr < 8; ++rr) {
            int row = rbase + rr;
            if (row < 32)      { wrow[rr] = Wq + row * Cn;        bias[rr] = bq[row]; }
            else if (row < 64) { wrow[rr] = Wk + (row - 32) * Cn; bias[rr] = bk[row - 32]; }
            else               { wrow[rr] = Wv + (row - 64) * Cn; bias[rr] = bv[row - 64]; }
        }
        float2 acc[16];
        #pragma unroll
        for (int k = 0; k < 16; ++k) acc[k] = make_float2(0.f, 0.f);

        #pragma unroll 4
        for (int c2 = 0; c2 < 64; ++c2) {
            uint2 u0 = *reinterpret_cast<const uint2*>(&x0[c2 * 2]);
            uint2 u1 = *reinterpret_cast<const uint2*>(&x1[c2 * 2]);
            float2 xa0 = bf2f2(u0.x), xb0 = bf2f2(u0.y);
            float2 xa1 = bf2f2(u1.x), xb1 = bf2f2(u1.y);
            #pragma unroll
            for (int rr = 0; rr < 8; ++rr) {
                float4 wv = __ldg(reinterpret_cast<const float4*>(wrow[rr]) + c2);
                float2 wlo = make_float2(wv.x, wv.y), whi = make_float2(wv.z, wv.w);
                acc[rr * 2]     = ffma2(wlo, xa0, acc[rr * 2]);
                acc[rr * 2]     = ffma2(whi, xb0, acc[rr * 2]);
                acc[rr * 2 + 1] = ffma2(wlo, xa1, acc[rr * 2 + 1]);
                acc[rr * 2 + 1] = ffma2(whi, xb1, acc[rr * 2 + 1]);
            }
        }
        #pragma unroll
        for (int rr = 0; rr < 8; ++rr) {
            int row = rbase + rr;
            float v0 = acc[rr * 2].x + acc[rr * 2].y + bias[rr];
            float v1 = acc[rr * 2 + 1].x + acc[rr * 2 + 1].y + bias[rr];
            if (row < 32) {
                g_Qb[((size_t)b * Ln + l0 + lane) * Dn + row]      = __float2bfloat16(v0 * qs);
                g_Qb[((size_t)b * Ln + l0 + lane + 32) * Dn + row] = __float2bfloat16(v1 * qs);
            } else if (row < 64) {
                int d = row - 32;
                g_Kb[((size_t)b * Ln + l0 + lane) * Dn + d]      = __float2bfloat16(v0);
                g_Kb[((size_t)b * Ln + l0 + lane + 32) * Dn + d] = __float2bfloat16(v1);
            } else {
                int o = row - 64;
                g_Vb[((size_t)b * Cn + o) * Ln + l0 + lane]      = __float2bfloat16(v0);
                g_Vb[((size_t)b * Cn + o) * Ln + l0 + lane + 32] = __float2bfloat16(v1);
            }
        }
    }
}

// ===========================================================================
// Kernel 2: HMMA flash attention, cp.async double-buffered, 512 threads.
// grid (L/128, 2, B). CTA: 128 queries x 128 channels (half of C).
// Warp w: rg = w>>1 (16 queries, 8 groups), ch = w&1 (64 channels).
// Dynamic smem (bytes):
//   [0, 10240)              Q [128][40] bf16
//   [10240 + bi*5120)       K [2][64][40] bf16
//   [20480 + bi*18432)      V [2][128][72] bf16  (region reused as f32 [64][132])
// ===========================================================================
#define SM_Q  0
#define SM_K(bi) (10240 + (bi) * 5120)
#define SM_V(bi) (20480 + (bi) * 18432)
#define SM_TOTAL (20480 + 2 * 18432)

__global__ __launch_bounds__(512, 1) void attn_kernel(
    const float* __restrict__ x,
    const float* __restrict__ gamma,
    float* __restrict__ out)
{
    extern __shared__ __align__(16) char dsm[];
    const int b = blockIdx.z, ch_half = blockIdx.y, i0 = blockIdx.x * 128;
    const int t = threadIdx.x;
    const int w = t >> 5, lane = t & 31;
    const int rg = w >> 1, ch = w & 1;

    const uint32_t sbase = smem_to_u32(dsm);
    __nv_bfloat16* Qsm = reinterpret_cast<__nv_bfloat16*>(dsm + SM_Q);

    const __nv_bfloat16* Qg = &g_Qb[((size_t)b * Ln + i0) * Dn];
    const __nv_bfloat16* Kg = &g_Kb[(size_t)b * Ln * Dn];
    const __nv_bfloat16* Vg = &g_Vb[((size_t)b * Cn + ch_half * 128) * Ln];

    // stage Q tile: 128 q x 32 d  (512 x uint4)
    {
        int q = t >> 2, dc = t & 3;
        uint4 v = *reinterpret_cast<const uint4*>(Qg + (size_t)q * Dn + dc * 8);
        *reinterpret_cast<uint4*>(&Qsm[q * 40 + dc * 8]) = v;
    }

    // prologue: issue chunk 0 loads
    if (t < 256) {
        int j = t >> 2, dc = t & 3;
        cp_async16(sbase + SM_K(0) + (j * 40 + dc * 8) * 2, Kg + (size_t)j * Dn + dc * 8);
    }
    {
        int c = t >> 3, k = t & 7;
        #pragma unroll
        for (int cc = 0; cc < 2; ++cc)
            cp_async16(sbase + SM_V(0) + ((c + cc * 64) * 72 + k * 8) * 2,
                       Vg + (size_t)(c + cc * 64) * Ln + k * 8);
    }
    CP_COMMIT();
    __syncthreads();

    // Q a-frags (k=0..15, 16..31), loaded once
    uint32_t aq[2][4];
    {
        uint32_t base = sbase + SM_Q + ((rg * 16 + (lane & 15)) * 40 + ((lane >> 4) & 1) * 8) * 2;
        ldmatrix_x4(aq[0][0], aq[0][1], aq[0][2], aq[0][3], base);
        ldmatrix_x4(aq[1][0], aq[1][1], aq[1][2], aq[1][3], base + 32);
    }

    const uint32_t kb_lane = (lane & 7) * 80 + ((lane >> 3) & 1) * 16;
    const uint32_t vb_lane = (lane & 7) * 144 + (lane >> 3) * 16;

    float of[8][4];
    #pragma unroll
    for (int n = 0; n < 8; ++n)
        #pragma unroll
        for (int k = 0; k < 4; ++k) of[n][k] = 0.f;
    float lsum0 = 0.f, lsum1 = 0.f;

    for (int cidx = 0; cidx < Ln / 64; ++cidx) {
        CP_WAIT0();
        __syncthreads();   // chunk cidx visible; all warps done with buf[cidx^1]

        // issue chunk cidx+1 into the other buffer (overlaps compute below)
        if (cidx + 1 < Ln / 64) {
            int j0n = (cidx + 1) * 64;
            int bi = (cidx + 1) & 1;
            if (t < 256) {
                int j = t >> 2, dc = t & 3;
                cp_async16(sbase + SM_K(bi) + (j * 40 + dc * 8) * 2,
                           Kg + (size_t)(j0n + j) * Dn + dc * 8);
            }
            int c = t >> 3, k = t & 7;
            #pragma unroll
            for (int cc = 0; cc < 2; ++cc)
                cp_async16(sbase + SM_V(bi) + ((c + cc * 64) * 72 + k * 8) * 2,
                           Vg + (size_t)(c + cc * 64) * Ln + j0n + k * 8);
        }
        CP_COMMIT();

        const uint32_t ks_u = sbase + SM_K(cidx & 1);
        const uint32_t vs_u = sbase + SM_V(cidx & 1);

        // S = Q K^T (16 x 64) -> exp -> P a-frags
        uint32_t pa[4][4];
        #pragma unroll
        for (int jt = 0; jt < 8; ++jt) {
            float s0 = 0.f, s1 = 0.f, s2 = 0.f, s3 = 0.f;
            uint32_t b0, b1;
            uint32_t kaddr = ks_u + jt * 640 + kb_lane;
            ldmatrix_x2(b0, b1, kaddr);
            mma_bf16(s0, s1, s2, s3, aq[0][0], aq[0][1], aq[0][2], aq[0][3], b0, b1);
            ldmatrix_x2(b0, b1, kaddr + 32);
            mma_bf16(s0, s1, s2, s3, aq[1][0], aq[1][1], aq[1][2], aq[1][3], b0, b1);

            float e0 = ex2f(s0), e1 = ex2f(s1), e2 = ex2f(s2), e3 = ex2f(s3);
            lsum0 += e0 + e1;
            lsum1 += e2 + e3;
            uint32_t plo, phi;
            CVT_BF16X2(plo, e0, e1);
            CVT_BF16X2(phi, e2, e3);
            int pt = jt >> 1;
            if ((jt & 1) == 0) { pa[pt][0] = plo; pa[pt][1] = phi; }
            else               { pa[pt][2] = plo; pa[pt][3] = phi; }
        }

        // O += P V^T : 8 n-tiles (64 channels), k = 64
        #pragma unroll
        for (int nt = 0; nt < 8; ++nt) {
            uint32_t vbase = vs_u + (uint32_t)(ch * 64 + nt * 8) * 144 + vb_lane;
            uint32_t b0, b1, b2, b3;
            ldmatrix_x4(b0, b1, b2, b3, vbase);
            mma_bf16(of[nt][0], of[nt][1], of[nt][2], of[nt][3],
                     pa[0][0], pa[0][1], pa[0][2], pa[0][3], b0, b1);
            mma_bf16(of[nt][0], of[nt][1], of[nt][2], of[nt][3],
                     pa[1][0], pa[1][1], pa[1][2], pa[1][3], b2, b3);
            ldmatrix_x4(b0, b1, b2, b3, vbase + 64);
            mma_bf16(of[nt][0], of[nt][1], of[nt][2], of[nt][3],
                     pa[2][0], pa[2][1], pa[2][2], pa[2][3], b0, b1);
            mma_bf16(of[nt][0], of[nt][1], of[nt][2], of[nt][3],
                     pa[3][0], pa[3][1], pa[3][2], pa[3][3], b2, b3);
        }
    }

    // row-sum reduction across the quad
    lsum0 += __shfl_xor_sync(0xFFFFFFFF, lsum0, 1);
    lsum0 += __shfl_xor_sync(0xFFFFFFFF, lsum0, 2);
    lsum1 += __shfl_xor_sync(0xFFFFFFFF, lsum1, 1);
    lsum1 += __shfl_xor_sync(0xFFFFFFFF, lsum1, 2);
    const float linv0 = 1.f / lsum0;
    const float linv1 = 1.f / lsum1;
    const float gam = __ldg(gamma);

    float* Tsm = reinterpret_cast<float*>(dsm + SM_V(0));   // [64][132] f32
    const float* xb = x + (size_t)b * Cn * Ln;
    float* ob = out + (size_t)b * Cn * Ln;

    for (int h = 0; h < 2; ++h) {
        __syncthreads();
        if (ch == h) {
            int q = rg * 16 + (lane >> 2);
            #pragma unroll
            for (int nt = 0; nt < 8; ++nt) {
                int cl = nt * 8 + (lane & 3) * 2;
                Tsm[cl * 132 + q]           = of[nt][0] * linv0;
                Tsm[(cl + 1) * 132 + q]     = of[nt][1] * linv0;
                Tsm[cl * 132 + q + 8]       = of[nt][2] * linv1;
                Tsm[(cl + 1) * 132 + q + 8] = of[nt][3] * linv1;
            }
        }
        __syncthreads();
        for (int idx = t; idx < 64 * 128; idx += 512) {
            int cl = idx >> 7, q = idx & 127;
            size_t off = (size_t)(ch_half * 128 + h * 64 + cl) * Ln + i0 + q;
            ob[off] = gam * Tsm[cl * 132 + q] + xb[off];
        }
    }
}

// ===========================================================================
extern "C" void kernel_launch(void* const* d_in, const int* in_sizes, int n_in,
                              void* d_out, int out_size)
{
    const float* x     = (const float*)d_in[0];
    const float* Wq    = (const float*)d_in[1];
    const float* bq    = (const float*)d_in[2];
    const float* Wk    = (const float*)d_in[3];
    const float* bk    = (const float*)d_in[4];
    const float* Wv    = (const float*)d_in[5];
    const float* bv    = (const float*)d_in[6];
    const float* gamma = (const float*)d_in[7];
    float* out = (float*)d_out;

    cudaFuncSetAttribute(attn_kernel, cudaFuncAttributeMaxDynamicSharedMemorySize, SM_TOTAL);

    qkv_kernel<<<dim3(Ln / 64, Bn), 256>>>(x, Wq, bq, Wk, bk, Wv, bv);
    attn_kernel<<<dim3(Ln / 128, 2, Bn), 512, SM_TOTAL>>>(x, gamma, out);
}

// round 7
// speedup vs baseline: 7.9790x; 1.3962x over previous
#include <cuda_runtime.h>
#include <cuda_bf16.h>
#include <cuda_fp16.h>
#include <cstdint>

#define Bn 8
#define Cn 256
#define Ln 2048
#define Dn 32

// scratch (device globals; no cudaMalloc allowed)
__device__ __nv_bfloat16 g_Qb[Bn * Ln * Dn];   // [b][l][d]  pre-scaled by scale*log2e
__device__ __nv_bfloat16 g_Kb[Bn * Ln * Dn];   // [b][l][d]
__device__ __nv_bfloat16 g_Vb[Bn * Cn * Ln];   // [b][c][l]
__device__ __half        g_Wh[320 * 256];      // fused W (Q rows pre-scaled), fp16
__device__ float         g_bias[320];          // fused bias (Q part pre-scaled)

// ============================ helpers ======================================
__device__ __forceinline__ uint32_t smem_to_u32(const void* p) {
    uint32_t a;
    asm("{ .reg .u64 t; cvta.to.shared.u64 t, %1; cvt.u32.u64 %0, t; }" : "=r"(a) : "l"(p));
    return a;
}
__device__ __forceinline__ float ex2f(float x) {
    float r; asm("ex2.approx.ftz.f32 %0, %1;" : "=f"(r) : "f"(x)); return r;
}
#define CVT_BF16X2(res, a, b) \
    asm("cvt.rn.bf16x2.f32 %0, %1, %2;" : "=r"(res) : "f"(b), "f"(a))
#define CVT_F16X2(res, a, b) \
    asm("cvt.rn.f16x2.f32 %0, %1, %2;" : "=r"(res) : "f"(b), "f"(a))

__device__ __forceinline__ void ldmatrix_x4(uint32_t& r0, uint32_t& r1, uint32_t& r2, uint32_t& r3, uint32_t addr) {
    asm volatile("ldmatrix.sync.aligned.m8n8.x4.shared.b16 {%0,%1,%2,%3}, [%4];"
                 : "=r"(r0), "=r"(r1), "=r"(r2), "=r"(r3) : "r"(addr));
}
__device__ __forceinline__ void ldmatrix_x2(uint32_t& r0, uint32_t& r1, uint32_t addr) {
    asm volatile("ldmatrix.sync.aligned.m8n8.x2.shared.b16 {%0,%1}, [%2];"
                 : "=r"(r0), "=r"(r1) : "r"(addr));
}
__device__ __forceinline__ void mma_bf16(float& c0, float& c1, float& c2, float& c3,
                                         uint32_t a0, uint32_t a1, uint32_t a2, uint32_t a3,
                                         uint32_t b0, uint32_t b1) {
    asm volatile("mma.sync.aligned.m16n8k16.row.col.f32.bf16.bf16.f32 "
                 "{%0,%1,%2,%3}, {%4,%5,%6,%7}, {%8,%9}, {%0,%1,%2,%3};"
                 : "+f"(c0), "+f"(c1), "+f"(c2), "+f"(c3)
                 : "r"(a0), "r"(a1), "r"(a2), "r"(a3), "r"(b0), "r"(b1));
}
__device__ __forceinline__ void mma_fp16(float& c0, float& c1, float& c2, float& c3,
                                         uint32_t a0, uint32_t a1, uint32_t a2, uint32_t a3,
                                         uint32_t b0, uint32_t b1) {
    asm volatile("mma.sync.aligned.m16n8k16.row.col.f32.f16.f16.f32 "
                 "{%0,%1,%2,%3}, {%4,%5,%6,%7}, {%8,%9}, {%0,%1,%2,%3};"
                 : "+f"(c0), "+f"(c1), "+f"(c2), "+f"(c3)
                 : "r"(a0), "r"(a1), "r"(a2), "r"(a3), "r"(b0), "r"(b1));
}
__device__ __forceinline__ void cp_async16(uint32_t saddr, const void* gptr) {
    asm volatile("cp.async.cg.shared.global [%0], [%1], 16;" :: "r"(saddr), "l"(gptr));
}
#define CP_COMMIT() asm volatile("cp.async.commit_group;" ::: "memory")
#define CP_WAIT0()  asm volatile("cp.async.wait_group 0;" ::: "memory")

// ===========================================================================
// Kernel 0: fuse W/bias into fp16 (Q rows pre-scaled by scale*log2e)
// grid 320, 256 threads.
// ===========================================================================
__global__ void prep_kernel(
    const float* __restrict__ Wq, const float* __restrict__ bq,
    const float* __restrict__ Wk, const float* __restrict__ bk,
    const float* __restrict__ Wv, const float* __restrict__ bv)
{
    const int row = blockIdx.x, c = threadIdx.x;
    const float qs = 1.4426950408889634f * 0.17677669529663687f;
    const float* src; float bsrc; float sc;
    if (row < 32)      { src = Wq + row * Cn;        bsrc = bq[row];      sc = qs; }
    else if (row < 64) { src = Wk + (row - 32) * Cn; bsrc = bk[row - 32]; sc = 1.f; }
    else               { src = Wv + (row - 64) * Cn; bsrc = bv[row - 64]; sc = 1.f; }
    g_Wh[row * 256 + c] = __float2half(src[c] * sc);
    if (c == 0) g_bias[row] = bsrc * sc;
}

// ===========================================================================
// Kernel 1: QKV projection as HMMA GEMM. grid (L/64, B), 256 threads.
// M = 64 l-positions (A = x tile, fp16, smem), N = 320 rows (B = W, direct LDG),
// K = 256 channels. Warp w: mg = w&3 (16 l), nh = w>>2 (160 rows).
// ===========================================================================
__global__ __launch_bounds__(256) void qkv_gemm(const float* __restrict__ x)
{
    __shared__ __align__(16) char smraw[36864];   // xs [64][132]u32 (33.8KB) / vt [256][72]bf16 (36.9KB)
    uint32_t* xs = reinterpret_cast<uint32_t*>(smraw);

    const int b = blockIdx.y, l0 = blockIdx.x * 64, t = threadIdx.x;
    const float* xb = x + (size_t)b * Cn * Ln;

    // stage x tile as fp16 pairs: xs[l][cp] = {x[2cp][l], x[2cp+1][l]}
    for (int idx = t; idx < 128 * 64; idx += 256) {
        int cp = idx >> 6, l = idx & 63;
        float f0 = xb[(size_t)(2 * cp) * Ln + l0 + l];
        float f1 = xb[(size_t)(2 * cp + 1) * Ln + l0 + l];
        uint32_t p; CVT_F16X2(p, f0, f1);
        xs[l * 132 + cp] = p;
    }
    __syncthreads();

    const int w = t >> 5, lane = t & 31;
    const int mg = w & 3, nh = w >> 2;
    const int nbase = nh * 160;

    float of[20][4];
    #pragma unroll
    for (int n = 0; n < 20; ++n)
        #pragma unroll
        for (int k = 0; k < 4; ++k) of[n][k] = 0.f;

    const uint32_t abase = smem_to_u32(xs)
        + (uint32_t)((mg * 16 + (lane & 15)) * 132) * 4 + ((lane >> 4) & 1) * 16;
    // W b-frag base: row = nbase + lane/4, k offset = (lane%4)*2
    const __half* wlane = g_Wh + (size_t)(nbase + (lane >> 2)) * 256 + (lane & 3) * 2;

    for (int ks = 0; ks < 16; ++ks) {
        uint32_t a0, a1, a2, a3;
        ldmatrix_x4(a0, a1, a2, a3, abase + ks * 32);
        const __half* wk = wlane + ks * 16;
        #pragma unroll
        for (int nt = 0; nt < 20; ++nt) {
            uint32_t b0 = *reinterpret_cast<const uint32_t*>(wk + nt * 8 * 256);
            uint32_t b1 = *reinterpret_cast<const uint32_t*>(wk + nt * 8 * 256 + 8);
            mma_fp16(of[nt][0], of[nt][1], of[nt][2], of[nt][3], a0, a1, a2, a3, b0, b1);
        }
    }
    __syncthreads();   // xs reads done; smem reused for V transpose

    __nv_bfloat16* vt = reinterpret_cast<__nv_bfloat16*>(smraw);   // [c][72]
    const int lq = l0 + mg * 16 + (lane >> 2);
    const int ll = mg * 16 + (lane >> 2);

    #pragma unroll
    for (int nt = 0; nt < 20; ++nt) {
        int n0 = nbase + nt * 8;
        int d = n0 + (lane & 3) * 2;
        float2 bs = __ldg(reinterpret_cast<const float2*>(&g_bias[d]));
        float v0 = of[nt][0] + bs.x, v1 = of[nt][1] + bs.y;
        float v2 = of[nt][2] + bs.x, v3 = of[nt][3] + bs.y;
        if (n0 < 32) {
            uint32_t p0, p1;
            CVT_BF16X2(p0, v0, v1);
            CVT_BF16X2(p1, v2, v3);
            *reinterpret_cast<uint32_t*>(&g_Qb[((size_t)b * Ln + lq) * Dn + d])     = p0;
            *reinterpret_cast<uint32_t*>(&g_Qb[((size_t)b * Ln + lq + 8) * Dn + d]) = p1;
        } else if (n0 < 64) {
            int dk = d - 32;
            uint32_t p0, p1;
            CVT_BF16X2(p0, v0, v1);
            CVT_BF16X2(p1, v2, v3);
            *reinterpret_cast<uint32_t*>(&g_Kb[((size_t)b * Ln + lq) * Dn + dk])     = p0;
            *reinterpret_cast<uint32_t*>(&g_Kb[((size_t)b * Ln + lq + 8) * Dn + dk]) = p1;
        } else {
            int c = d - 64;
            vt[c * 72 + ll]           = __float2bfloat16(v0);
            vt[(c + 1) * 72 + ll]     = __float2bfloat16(v1);
            vt[c * 72 + ll + 8]       = __float2bfloat16(v2);
            vt[(c + 1) * 72 + ll + 8] = __float2bfloat16(v3);
        }
    }
    __syncthreads();

    // coalesced V store: [c][l], uint4 along l
    __nv_bfloat16* Vg = g_Vb + (size_t)b * Cn * Ln;
    for (int idx = t; idx < 2048; idx += 256) {
        int c = idx >> 3, k8 = idx & 7;
        *reinterpret_cast<uint4*>(Vg + (size_t)c * Ln + l0 + k8 * 8) =
            *reinterpret_cast<const uint4*>(&vt[c * 72 + k8 * 8]);
    }
}

// ===========================================================================
// Kernel 2: HMMA flash attention, cp.async double-buffered, 512 threads.
// grid (L/128, 2, B). CTA: 128 queries x 128 channels (half of C).
// (unchanged from R6)
// ===========================================================================
#define SM_Q  0
#define SM_K(bi) (10240 + (bi) * 5120)
#define SM_V(bi) (20480 + (bi) * 18432)
#define SM_TOTAL (20480 + 2 * 18432)

__global__ __launch_bounds__(512, 1) void attn_kernel(
    const float* __restrict__ x,
    const float* __restrict__ gamma,
    float* __restrict__ out)
{
    extern __shared__ __align__(16) char dsm[];
    const int b = blockIdx.z, ch_half = blockIdx.y, i0 = blockIdx.x * 128;
    const int t = threadIdx.x;
    const int w = t >> 5, lane = t & 31;
    const int rg = w >> 1, ch = w & 1;

    const uint32_t sbase = smem_to_u32(dsm);
    __nv_bfloat16* Qsm = reinterpret_cast<__nv_bfloat16*>(dsm + SM_Q);

    const __nv_bfloat16* Qg = &g_Qb[((size_t)b * Ln + i0) * Dn];
    const __nv_bfloat16* Kg = &g_Kb[(size_t)b * Ln * Dn];
    const __nv_bfloat16* Vg = &g_Vb[((size_t)b * Cn + ch_half * 128) * Ln];

    {
        int q = t >> 2, dc = t & 3;
        uint4 v = *reinterpret_cast<const uint4*>(Qg + (size_t)q * Dn + dc * 8);
        *reinterpret_cast<uint4*>(&Qsm[q * 40 + dc * 8]) = v;
    }

    if (t < 256) {
        int j = t >> 2, dc = t & 3;
        cp_async16(sbase + SM_K(0) + (j * 40 + dc * 8) * 2, Kg + (size_t)j * Dn + dc * 8);
    }
    {
        int c = t >> 3, k = t & 7;
        #pragma unroll
        for (int cc = 0; cc < 2; ++cc)
            cp_async16(sbase + SM_V(0) + ((c + cc * 64) * 72 + k * 8) * 2,
                       Vg + (size_t)(c + cc * 64) * Ln + k * 8);
    }
    CP_COMMIT();
    __syncthreads();

    uint32_t aq[2][4];
    {
        uint32_t base = sbase + SM_Q + ((rg * 16 + (lane & 15)) * 40 + ((lane >> 4) & 1) * 8) * 2;
        ldmatrix_x4(aq[0][0], aq[0][1], aq[0][2], aq[0][3], base);
        ldmatrix_x4(aq[1][0], aq[1][1], aq[1][2], aq[1][3], base + 32);
    }

    const uint32_t kb_lane = (lane & 7) * 80 + ((lane >> 3) & 1) * 16;
    const uint32_t vb_lane = (lane & 7) * 144 + (lane >> 3) * 16;

    float of[8][4];
    #pragma unroll
    for (int n = 0; n < 8; ++n)
        #pragma unroll
        for (int k = 0; k < 4; ++k) of[n][k] = 0.f;
    float lsum0 = 0.f, lsum1 = 0.f;

    for (int cidx = 0; cidx < Ln / 64; ++cidx) {
        CP_WAIT0();
        __syncthreads();

        if (cidx + 1 < Ln / 64) {
            int j0n = (cidx + 1) * 64;
            int bi = (cidx + 1) & 1;
            if (t < 256) {
                int j = t >> 2, dc = t & 3;
                cp_async16(sbase + SM_K(bi) + (j * 40 + dc * 8) * 2,
                           Kg + (size_t)(j0n + j) * Dn + dc * 8);
            }
            int c = t >> 3, k = t & 7;
            #pragma unroll
            for (int cc = 0; cc < 2; ++cc)
                cp_async16(sbase + SM_V(bi) + ((c + cc * 64) * 72 + k * 8) * 2,
                           Vg + (size_t)(c + cc * 64) * Ln + j0n + k * 8);
        }
        CP_COMMIT();

        const uint32_t ks_u = sbase + SM_K(cidx & 1);
        const uint32_t vs_u = sbase + SM_V(cidx & 1);

        uint32_t pa[4][4];
        #pragma unroll
        for (int jt = 0; jt < 8; ++jt) {
            float s0 = 0.f, s1 = 0.f, s2 = 0.f, s3 = 0.f;
            uint32_t b0, b1;
            uint32_t kaddr = ks_u + jt * 640 + kb_lane;
            ldmatrix_x2(b0, b1, kaddr);
            mma_bf16(s0, s1, s2, s3, aq[0][0], aq[0][1], aq[0][2], aq[0][3], b0, b1);
            ldmatrix_x2(b0, b1, kaddr + 32);
            mma_bf16(s0, s1, s2, s3, aq[1][0], aq[1][1], aq[1][2], aq[1][3], b0, b1);

            float e0 = ex2f(s0), e1 = ex2f(s1), e2 = ex2f(s2), e3 = ex2f(s3);
            lsum0 += e0 + e1;
            lsum1 += e2 + e3;
            uint32_t plo, phi;
            CVT_BF16X2(plo, e0, e1);
            CVT_BF16X2(phi, e2, e3);
            int pt = jt >> 1;
            if ((jt & 1) == 0) { pa[pt][0] = plo; pa[pt][1] = phi; }
            else               { pa[pt][2] = plo; pa[pt][3] = phi; }
        }

        #pragma unroll
        for (int nt = 0; nt < 8; ++nt) {
            uint32_t vbase = vs_u + (uint32_t)(ch * 64 + nt * 8) * 144 + vb_lane;
            uint32_t b0, b1, b2, b3;
            ldmatrix_x4(b0, b1, b2, b3, vbase);
            mma_bf16(of[nt][0], of[nt][1], of[nt][2], of[nt][3],
                     pa[0][0], pa[0][1], pa[0][2], pa[0][3], b0, b1);
            mma_bf16(of[nt][0], of[nt][1], of[nt][2], of[nt][3],
                     pa[1][0], pa[1][1], pa[1][2], pa[1][3], b2, b3);
            ldmatrix_x4(b0, b1, b2, b3, vbase + 64);
            mma_bf16(of[nt][0], of[nt][1], of[nt][2], of[nt][3],
                     pa[2][0], pa[2][1], pa[2][2], pa[2][3], b0, b1);
            mma_bf16(of[nt][0], of[nt][1], of[nt][2], of[nt][3],
                     pa[3][0], pa[3][1], pa[3][2], pa[3][3], b2, b3);
        }
    }

    lsum0 += __shfl_xor_sync(0xFFFFFFFF, lsum0, 1);
    lsum0 += __shfl_xor_sync(0xFFFFFFFF, lsum0, 2);
    lsum1 += __shfl_xor_sync(0xFFFFFFFF, lsum1, 1);
    lsum1 += __shfl_xor_sync(0xFFFFFFFF, lsum1, 2);
    const float linv0 = 1.f / lsum0;
    const float linv1 = 1.f / lsum1;
    const float gam = __ldg(gamma);

    float* Tsm = reinterpret_cast<float*>(dsm + SM_V(0));   // [64][132] f32
    const float* xb = x + (size_t)b * Cn * Ln;
    float* ob = out + (size_t)b * Cn * Ln;

    for (int h = 0; h < 2; ++h) {
        __syncthreads();
        if (ch == h) {
            int q = rg * 16 + (lane >> 2);
            #pragma unroll
            for (int nt = 0; nt < 8; ++nt) {
                int cl = nt * 8 + (lane & 3) * 2;
                Tsm[cl * 132 + q]           = of[nt][0] * linv0;
                Tsm[(cl + 1) * 132 + q]     = of[nt][1] * linv0;
                Tsm[cl * 132 + q + 8]       = of[nt][2] * linv1;
                Tsm[(cl + 1) * 132 + q + 8] = of[nt][3] * linv1;
            }
        }
        __syncthreads();
        for (int idx = t; idx < 64 * 128; idx += 512) {
            int cl = idx >> 7, q = idx & 127;
            size_t off = (size_t)(ch_half * 128 + h * 64 + cl) * Ln + i0 + q;
            ob[off] = gam * Tsm[cl * 132 + q] + xb[off];
        }
    }
}

// ===========================================================================
extern "C" void kernel_launch(void* const* d_in, const int* in_sizes, int n_in,
                              void* d_out, int out_size)
{
    const float* x     = (const float*)d_in[0];
    const float* Wq    = (const float*)d_in[1];
    const float* bq    = (const float*)d_in[2];
    const float* Wk    = (const float*)d_in[3];
    const float* bk    = (const float*)d_in[4];
    const float* Wv    = (const float*)d_in[5];
    const float* bv    = (const float*)d_in[6];
    const float* gamma = (const float*)d_in[7];
    float* out = (float*)d_out;

    cudaFuncSetAttribute(attn_kernel, cudaFuncAttributeMaxDynamicSharedMemorySize, SM_TOTAL);

    prep_kernel<<<320, 256>>>(Wq, bq, Wk, bk, Wv, bv);
    qkv_gemm<<<dim3(Ln / 64, Bn), 256>>>(x);
    attn_kernel<<<dim3(Ln / 128, 2, Bn), 512, SM_TOTAL>>>(x, gamma, out);
}

// round 8
// speedup vs baseline: 8.2090x; 1.0288x over previous
#include <cuda_runtime.h>
#include <cuda_bf16.h>
#include <cuda_fp16.h>
#include <cstdint>

#define Bn 8
#define Cn 256
#define Ln 2048
#define Dn 32

// scratch (device globals; no cudaMalloc allowed)
__device__ __nv_bfloat16 g_Qb[Bn * Ln * Dn];   // [b][l][d]  pre-scaled by scale*log2e
__device__ __nv_bfloat16 g_Kb[Bn * Ln * Dn];   // [b][l][d]
__device__ __nv_bfloat16 g_Vb[Bn * Cn * Ln];   // [b][c][l]
__device__ __half        g_Wh[320 * 256];      // fused W (Q rows pre-scaled), fp16
__device__ float         g_bias[320];          // fused bias (Q part pre-scaled)

// ============================ helpers ======================================
__device__ __forceinline__ uint32_t smem_to_u32(const void* p) {
    uint32_t a;
    asm("{ .reg .u64 t; cvta.to.shared.u64 t, %1; cvt.u32.u64 %0, t; }" : "=r"(a) : "l"(p));
    return a;
}
__device__ __forceinline__ float ex2f(float x) {
    float r; asm("ex2.approx.ftz.f32 %0, %1;" : "=f"(r) : "f"(x)); return r;
}
#define CVT_BF16X2(res, a, b) \
    asm("cvt.rn.bf16x2.f32 %0, %1, %2;" : "=r"(res) : "f"(b), "f"(a))
#define CVT_F16X2(res, a, b) \
    asm("cvt.rn.f16x2.f32 %0, %1, %2;" : "=r"(res) : "f"(b), "f"(a))

__device__ __forceinline__ void ldmatrix_x4(uint32_t& r0, uint32_t& r1, uint32_t& r2, uint32_t& r3, uint32_t addr) {
    asm volatile("ldmatrix.sync.aligned.m8n8.x4.shared.b16 {%0,%1,%2,%3}, [%4];"
                 : "=r"(r0), "=r"(r1), "=r"(r2), "=r"(r3) : "r"(addr));
}
__device__ __forceinline__ void ldmatrix_x2(uint32_t& r0, uint32_t& r1, uint32_t addr) {
    asm volatile("ldmatrix.sync.aligned.m8n8.x2.shared.b16 {%0,%1}, [%2];"
                 : "=r"(r0), "=r"(r1) : "r"(addr));
}
__device__ __forceinline__ void mma_bf16(float& c0, float& c1, float& c2, float& c3,
                                         uint32_t a0, uint32_t a1, uint32_t a2, uint32_t a3,
                                         uint32_t b0, uint32_t b1) {
    asm volatile("mma.sync.aligned.m16n8k16.row.col.f32.bf16.bf16.f32 "
                 "{%0,%1,%2,%3}, {%4,%5,%6,%7}, {%8,%9}, {%0,%1,%2,%3};"
                 : "+f"(c0), "+f"(c1), "+f"(c2), "+f"(c3)
                 : "r"(a0), "r"(a1), "r"(a2), "r"(a3), "r"(b0), "r"(b1));
}
__device__ __forceinline__ void mma_fp16(float& c0, float& c1, float& c2, float& c3,
                                         uint32_t a0, uint32_t a1, uint32_t a2, uint32_t a3,
                                         uint32_t b0, uint32_t b1) {
    asm volatile("mma.sync.aligned.m16n8k16.row.col.f32.f16.f16.f32 "
                 "{%0,%1,%2,%3}, {%4,%5,%6,%7}, {%8,%9}, {%0,%1,%2,%3};"
                 : "+f"(c0), "+f"(c1), "+f"(c2), "+f"(c3)
                 : "r"(a0), "r"(a1), "r"(a2), "r"(a3), "r"(b0), "r"(b1));
}
__device__ __forceinline__ void cp_async16(uint32_t saddr, const void* gptr) {
    asm volatile("cp.async.cg.shared.global [%0], [%1], 16;" :: "r"(saddr), "l"(gptr));
}
#define CP_COMMIT() asm volatile("cp.async.commit_group;" ::: "memory")
#define CP_WAIT0()  asm volatile("cp.async.wait_group 0;" ::: "memory")
#define BAR_SYNC(id, n) asm volatile("bar.sync %0, %1;" :: "r"(id), "r"(n) : "memory")

// ===========================================================================
// Kernel 0: fuse W/bias into fp16 (Q rows pre-scaled by scale*log2e)
// ===========================================================================
__global__ void prep_kernel(
    const float* __restrict__ Wq, const float* __restrict__ bq,
    const float* __restrict__ Wk, const float* __restrict__ bk,
    const float* __restrict__ Wv, const float* __restrict__ bv)
{
    const int row = blockIdx.x, c = threadIdx.x;
    const float qs = 1.4426950408889634f * 0.17677669529663687f;
    const float* src; float bsrc; float sc;
    if (row < 32)      { src = Wq + row * Cn;        bsrc = bq[row];      sc = qs; }
    else if (row < 64) { src = Wk + (row - 32) * Cn; bsrc = bk[row - 32]; sc = 1.f; }
    else               { src = Wv + (row - 64) * Cn; bsrc = bv[row - 64]; sc = 1.f; }
    g_Wh[row * 256 + c] = __float2half(src[c] * sc);
    if (c == 0) g_bias[row] = bsrc * sc;
}

// ===========================================================================
// Kernel 1: QKV projection as HMMA GEMM. grid (L/128, B), 512 threads.
// M = 128 l (A = x tile fp16 smem), N = 320 rows (B = W direct LDG), K = 256.
// Warp w: mg = w&7 (16 l), nh = w>>3 (160 rows).
// Dynamic smem: xs [128][132]u32 (67584B) reused as vt [256][136]bf16 (69632B)
// ===========================================================================
#define QKV_SMEM 69632

__global__ __launch_bounds__(512) void qkv_gemm(const float* __restrict__ x)
{
    extern __shared__ __align__(16) char qsmraw[];
    uint32_t* xs = reinterpret_cast<uint32_t*>(qsmraw);

    const int b = blockIdx.y, l0 = blockIdx.x * 128, t = threadIdx.x;
    const float* xb = x + (size_t)b * Cn * Ln;

    // stage x tile as fp16 pairs: xs[l][cp] = {x[2cp][l], x[2cp+1][l]}
    for (int idx = t; idx < 128 * 128; idx += 512) {
        int cp = idx >> 7, l = idx & 127;
        float f0 = xb[(size_t)(2 * cp) * Ln + l0 + l];
        float f1 = xb[(size_t)(2 * cp + 1) * Ln + l0 + l];
        uint32_t p; CVT_F16X2(p, f0, f1);
        xs[l * 132 + cp] = p;
    }
    __syncthreads();

    const int w = t >> 5, lane = t & 31;
    const int mg = w & 7, nh = w >> 3;
    const int nbase = nh * 160;

    float of[20][4];
    #pragma unroll
    for (int n = 0; n < 20; ++n)
        #pragma unroll
        for (int k = 0; k < 4; ++k) of[n][k] = 0.f;

    const uint32_t abase = smem_to_u32(xs)
        + (uint32_t)((mg * 16 + (lane & 15)) * 132) * 4 + ((lane >> 4) & 1) * 16;
    const __half* wlane = g_Wh + (size_t)(nbase + (lane >> 2)) * 256 + (lane & 3) * 2;

    for (int ks = 0; ks < 16; ++ks) {
        uint32_t a0, a1, a2, a3;
        ldmatrix_x4(a0, a1, a2, a3, abase + ks * 32);
        const __half* wk = wlane + ks * 16;
        #pragma unroll
        for (int nt = 0; nt < 20; ++nt) {
            uint32_t b0 = *reinterpret_cast<const uint32_t*>(wk + nt * 8 * 256);
            uint32_t b1 = *reinterpret_cast<const uint32_t*>(wk + nt * 8 * 256 + 8);
            mma_fp16(of[nt][0], of[nt][1], of[nt][2], of[nt][3], a0, a1, a2, a3, b0, b1);
        }
    }
    __syncthreads();   // xs reads done; smem reused for V transpose

    __nv_bfloat16* vt = reinterpret_cast<__nv_bfloat16*>(qsmraw);   // [256][136]
    const int lq = l0 + mg * 16 + (lane >> 2);
    const int ll = mg * 16 + (lane >> 2);

    #pragma unroll
    for (int nt = 0; nt < 20; ++nt) {
        int n0 = nbase + nt * 8;
        int d = n0 + (lane & 3) * 2;
        float2 bs = __ldg(reinterpret_cast<const float2*>(&g_bias[d]));
        float v0 = of[nt][0] + bs.x, v1 = of[nt][1] + bs.y;
        float v2 = of[nt][2] + bs.x, v3 = of[nt][3] + bs.y;
        if (n0 < 32) {
            uint32_t p0, p1;
            CVT_BF16X2(p0, v0, v1);
            CVT_BF16X2(p1, v2, v3);
            *reinterpret_cast<uint32_t*>(&g_Qb[((size_t)b * Ln + lq) * Dn + d])     = p0;
            *reinterpret_cast<uint32_t*>(&g_Qb[((size_t)b * Ln + lq + 8) * Dn + d]) = p1;
        } else if (n0 < 64) {
            int dk = d - 32;
            uint32_t p0, p1;
            CVT_BF16X2(p0, v0, v1);
            CVT_BF16X2(p1, v2, v3);
            *reinterpret_cast<uint32_t*>(&g_Kb[((size_t)b * Ln + lq) * Dn + dk])     = p0;
            *reinterpret_cast<uint32_t*>(&g_Kb[((size_t)b * Ln + lq + 8) * Dn + dk]) = p1;
        } else {
            int c = d - 64;
            vt[c * 136 + ll]           = __float2bfloat16(v0);
            vt[(c + 1) * 136 + ll]     = __float2bfloat16(v1);
            vt[c * 136 + ll + 8]       = __float2bfloat16(v2);
            vt[(c + 1) * 136 + ll + 8] = __float2bfloat16(v3);
        }
    }
    __syncthreads();

    // coalesced V store: [c][l], uint4 along l
    __nv_bfloat16* Vg = g_Vb + (size_t)b * Cn * Ln;
    for (int idx = t; idx < 256 * 16; idx += 512) {
        int c = idx >> 4, k8 = idx & 15;
        *reinterpret_cast<uint4*>(Vg + (size_t)c * Ln + l0 + k8 * 8) =
            *reinterpret_cast<const uint4*>(&vt[c * 136 + k8 * 8]);
    }
}

// ===========================================================================
// Kernel 2: HMMA flash attention. 128-j chunks, cp.async double-buffered,
// warp-pair QK/exp dedup via P-fragment exchange. 512 threads.
// grid (L/128, 2, B). CTA: 128 q x 128 ch. Warp w: qg = w>>1, ch = w&1.
// Smem (bytes):
//   [0, 10240)            Q  [128][40] bf16
//   SM_K(bi)              K  [2][128][40] bf16      (10240 each)
//   SM_V(bi)              V  [2][128c][136] bf16    (34816 each; buf0 reused f32 [64][132])
//   SM_P + w*2048         P exchange slots (16 x 2048)
//   SM_LS + w*256         row-sum exchange (16 x 256)
// ===========================================================================
#define SM_K(bi) (10240 + (bi) * 10240)
#define SM_V(bi) (30720 + (bi) * 34816)
#define SM_P     100352
#define SM_LS    133120
#define SM_TOTAL 137216

__global__ __launch_bounds__(512, 1) void attn_kernel(
    const float* __restrict__ x,
    const float* __restrict__ gamma,
    float* __restrict__ out)
{
    extern __shared__ __align__(16) char dsm[];
    const int b = blockIdx.z, ch_half = blockIdx.y, i0 = blockIdx.x * 128;
    const int t = threadIdx.x;
    const int w = t >> 5, lane = t & 31;
    const int qg = w >> 1, ch = w & 1;

    const uint32_t sbase = smem_to_u32(dsm);
    __nv_bfloat16* Qsm = reinterpret_cast<__nv_bfloat16*>(dsm);

    const __nv_bfloat16* Qg = &g_Qb[((size_t)b * Ln + i0) * Dn];
    const __nv_bfloat16* Kg = &g_Kb[(size_t)b * Ln * Dn];
    const __nv_bfloat16* Vg = &g_Vb[((size_t)b * Cn + ch_half * 128) * Ln];

    // stage Q tile: 128 q x 32 d (512 x uint4)
    {
        int q = t >> 2, dc = t & 3;
        uint4 v = *reinterpret_cast<const uint4*>(Qg + (size_t)q * Dn + dc * 8);
        *reinterpret_cast<uint4*>(&Qsm[q * 40 + dc * 8]) = v;
    }

    // prologue: chunk 0 loads. K: 128j x 4 dchunks = 512 ops (1/thread);
    // V: 128c x 16 jchunks = 2048 ops (4/thread)
    {
        int j = t >> 2, dc = t & 3;
        cp_async16(sbase + SM_K(0) + j * 80 + dc * 16, Kg + (size_t)j * Dn + dc * 8);
        #pragma unroll
        for (int i = 0; i < 4; ++i) {
            int idx = t + i * 512;
            int c = idx >> 4, jc = idx & 15;
            cp_async16(sbase + SM_V(0) + c * 272 + jc * 16, Vg + (size_t)c * Ln + jc * 8);
        }
    }
    CP_COMMIT();
    __syncthreads();

    // Q a-frags, loaded once
    uint32_t aq[2][4];
    {
        uint32_t base = sbase + ((qg * 16 + (lane & 15)) * 40 + ((lane >> 4) & 1) * 8) * 2;
        ldmatrix_x4(aq[0][0], aq[0][1], aq[0][2], aq[0][3], base);
        ldmatrix_x4(aq[1][0], aq[1][1], aq[1][2], aq[1][3], base + 32);
    }

    const uint32_t kb_lane = (lane & 7) * 80 + ((lane >> 3) & 1) * 16;
    const uint32_t vb_lane = (lane & 7) * 272 + (lane >> 3) * 16;
    const uint32_t myslot  = sbase + SM_P + w * 2048 + lane * 16;
    const uint32_t pairslot= sbase + SM_P + (qg * 2) * 2048 + lane * 16;  // slot of ch==0 warp
    const int barid = 1 + qg;

    float of[8][4];
    #pragma unroll
    for (int n = 0; n < 8; ++n)
        #pragma unroll
        for (int k = 0; k < 4; ++k) of[n][k] = 0.f;
    float lsum0 = 0.f, lsum1 = 0.f;

    for (int cidx = 0; cidx < Ln / 128; ++cidx) {
        CP_WAIT0();
        __syncthreads();   // chunk data visible; everyone done with other buffer & P slots

        // issue chunk cidx+1
        if (cidx + 1 < Ln / 128) {
            int j0n = (cidx + 1) * 128;
            int bi = (cidx + 1) & 1;
            int j = t >> 2, dc = t & 3;
            cp_async16(sbase + SM_K(bi) + j * 80 + dc * 16,
                       Kg + (size_t)(j0n + j) * Dn + dc * 8);
            #pragma unroll
            for (int i = 0; i < 4; ++i) {
                int idx = t + i * 512;
                int c = idx >> 4, jc = idx & 15;
                cp_async16(sbase + SM_V(bi) + c * 272 + jc * 16,
                           Vg + (size_t)c * Ln + j0n + jc * 8);
            }
        }
        CP_COMMIT();

        const uint32_t ks_u = sbase + SM_K(cidx & 1);
        const uint32_t vs_u = sbase + SM_V(cidx & 1);

        // S = Q K^T for MY 64-j half only -> exp -> pa[4][4]
        uint32_t pa[4][4];
        {
            const uint32_t kh = ks_u + (uint32_t)(ch * 64) * 80 + kb_lane;
            #pragma unroll
            for (int jt = 0; jt < 8; ++jt) {
                float s0 = 0.f, s1 = 0.f, s2 = 0.f, s3 = 0.f;
                uint32_t b0, b1;
                uint32_t kaddr = kh + jt * 640;
                ldmatrix_x2(b0, b1, kaddr);
                mma_bf16(s0, s1, s2, s3, aq[0][0], aq[0][1], aq[0][2], aq[0][3], b0, b1);
                ldmatrix_x2(b0, b1, kaddr + 32);
                mma_bf16(s0, s1, s2, s3, aq[1][0], aq[1][1], aq[1][2], aq[1][3], b0, b1);

                float e0 = ex2f(s0), e1 = ex2f(s1), e2 = ex2f(s2), e3 = ex2f(s3);
                lsum0 += e0 + e1;
                lsum1 += e2 + e3;
                uint32_t plo, phi;
                CVT_BF16X2(plo, e0, e1);
                CVT_BF16X2(phi, e2, e3);
                int pt = jt >> 1;
                if ((jt & 1) == 0) { pa[pt][0] = plo; pa[pt][1] = phi; }
                else               { pa[pt][2] = plo; pa[pt][3] = phi; }
            }
        }
        // publish my P frags, sync with pair warp
        #pragma unroll
        for (int pt = 0; pt < 4; ++pt) {
            uint4 v = make_uint4(pa[pt][0], pa[pt][1], pa[pt][2], pa[pt][3]);
            *reinterpret_cast<uint4*>(dsm + (myslot - sbase) + pt * 512) = v;
        }
        BAR_SYNC(barid, 64);

        // O += P V^T over both k-halves (j 0:63 from ch0's P, j 64:127 from ch1's)
        #pragma unroll
        for (int h = 0; h < 2; ++h) {
            uint32_t pf[4][4];
            if (h == ch) {
                #pragma unroll
                for (int pt = 0; pt < 4; ++pt)
                    #pragma unroll
                    for (int r = 0; r < 4; ++r) pf[pt][r] = pa[pt][r];
            } else {
                #pragma unroll
                for (int pt = 0; pt < 4; ++pt) {
                    uint4 v = *reinterpret_cast<const uint4*>(
                        dsm + (pairslot - sbase) + h * 2048 + pt * 512);
                    pf[pt][0] = v.x; pf[pt][1] = v.y; pf[pt][2] = v.z; pf[pt][3] = v.w;
                }
            }
            #pragma unroll
            for (int nt = 0; nt < 8; ++nt) {
                uint32_t vbase = vs_u + (uint32_t)(ch * 64 + nt * 8) * 272 + h * 128 + vb_lane;
                uint32_t b0, b1, b2, b3;
                ldmatrix_x4(b0, b1, b2, b3, vbase);
                mma_bf16(of[nt][0], of[nt][1], of[nt][2], of[nt][3],
                         pf[0][0], pf[0][1], pf[0][2], pf[0][3], b0, b1);
                mma_bf16(of[nt][0], of[nt][1], of[nt][2], of[nt][3],
                         pf[1][0], pf[1][1], pf[1][2], pf[1][3], b2, b3);
                ldmatrix_x4(b0, b1, b2, b3, vbase + 64);
                mma_bf16(of[nt][0], of[nt][1], of[nt][2], of[nt][3],
                         pf[2][0], pf[2][1], pf[2][2], pf[2][3], b0, b1);
                mma_bf16(of[nt][0], of[nt][1], of[nt][2], of[nt][3],
                         pf[3][0], pf[3][1], pf[3][2], pf[3][3], b2, b3);
            }
        }
    }

    // row sums: quad-reduce, then combine across the warp pair
    lsum0 += __shfl_xor_sync(0xFFFFFFFF, lsum0, 1);
    lsum0 += __shfl_xor_sync(0xFFFFFFFF, lsum0, 2);
    lsum1 += __shfl_xor_sync(0xFFFFFFFF, lsum1, 1);
    lsum1 += __shfl_xor_sync(0xFFFFFFFF, lsum1, 2);
    {
        float2* ls = reinterpret_cast<float2*>(dsm + SM_LS + w * 256);
        ls[lane] = make_float2(lsum0, lsum1);
        BAR_SYNC(barid, 64);
        const float2* lsp = reinterpret_cast<const float2*>(dsm + SM_LS + (w ^ 1) * 256);
        float2 o = lsp[lane];
        lsum0 += o.x;
        lsum1 += o.y;
    }
    const float linv0 = 1.f / lsum0;
    const float linv1 = 1.f / lsum1;
    const float gam = __ldg(gamma);

    float* Tsm = reinterpret_cast<float*>(dsm + SM_V(0));   // [64][132] f32
    const float* xb = x + (size_t)b * Cn * Ln;
    float* ob = out + (size_t)b * Cn * Ln;

    for (int h = 0; h < 2; ++h) {
        __syncthreads();
        if (ch == h) {
            int q = qg * 16 + (lane >> 2);
            #pragma unroll
            for (int nt = 0; nt < 8; ++nt) {
                int cl = nt * 8 + (lane & 3) * 2;
                Tsm[cl * 132 + q]           = of[nt][0] * linv0;
                Tsm[(cl + 1) * 132 + q]     = of[nt][1] * linv0;
                Tsm[cl * 132 + q + 8]       = of[nt][2] * linv1;
                Tsm[(cl + 1) * 132 + q + 8] = of[nt][3] * linv1;
            }
        }
        __syncthreads();
        for (int idx = t; idx < 64 * 128; idx += 512) {
            int cl = idx >> 7, q = idx & 127;
            size_t off = (size_t)(ch_half * 128 + h * 64 + cl) * Ln + i0 + q;
            ob[off] = gam * Tsm[cl * 132 + q] + xb[off];
        }
    }
}

// ===========================================================================
extern "C" void kernel_launch(void* const* d_in, const int* in_sizes, int n_in,
                              void* d_out, int out_size)
{
    const float* x     = (const float*)d_in[0];
    const float* Wq    = (const float*)d_in[1];
    const float* bq    = (const float*)d_in[2];
    const float* Wk    = (const float*)d_in[3];
    const float* bk    = (const float*)d_in[4];
    const float* Wv    = (const float*)d_in[5];
    const float* bv    = (const float*)d_in[6];
    const float* gamma = (const float*)d_in[7];
    float* out = (float*)d_out;

    cudaFuncSetAttribute(qkv_gemm, cudaFuncAttributeMaxDynamicSharedMemorySize, QKV_SMEM);
    cudaFuncSetAttribute(attn_kernel, cudaFuncAttributeMaxDynamicSharedMemorySize, SM_TOTAL);

    prep_kernel<<<320, 256>>>(Wq, bq, Wk, bk, Wv, bv);
    qkv_gemm<<<dim3(Ln / 128, Bn), 512, QKV_SMEM>>>(x);
    attn_kernel<<<dim3(Ln / 128, 2, Bn), 512, SM_TOTAL>>>(x, gamma, out);
}

// round 9
// speedup vs baseline: 10.3719x; 1.2635x over previous
#include <cuda_runtime.h>
#include <cuda_bf16.h>
#include <cuda_fp16.h>
#include <cstdint>

#define Bn 8
#define Cn 256
#define Ln 2048
#define Dn 32

// scratch (device globals; no cudaMalloc allowed)
__device__ __nv_bfloat16 g_Qb[Bn * Ln * Dn];   // [b][l][d]  pre-scaled by scale*log2e
__device__ __nv_bfloat16 g_Kb[Bn * Ln * Dn];   // [b][l][d]
__device__ __nv_bfloat16 g_Vb[Bn * Cn * Ln];   // [b][c][l]

// ============================ helpers ======================================
__device__ __forceinline__ uint32_t smem_to_u32(const void* p) {
    uint32_t a;
    asm("{ .reg .u64 t; cvta.to.shared.u64 t, %1; cvt.u32.u64 %0, t; }" : "=r"(a) : "l"(p));
    return a;
}
__device__ __forceinline__ float ex2f(float x) {
    float r; asm("ex2.approx.ftz.f32 %0, %1;" : "=f"(r) : "f"(x)); return r;
}
#define CVT_BF16X2(res, a, b) \
    asm("cvt.rn.bf16x2.f32 %0, %1, %2;" : "=r"(res) : "f"(b), "f"(a))
#define CVT_F16X2(res, a, b) \
    asm("cvt.rn.f16x2.f32 %0, %1, %2;" : "=r"(res) : "f"(b), "f"(a))

__device__ __forceinline__ void ldmatrix_x4(uint32_t& r0, uint32_t& r1, uint32_t& r2, uint32_t& r3, uint32_t addr) {
    asm volatile("ldmatrix.sync.aligned.m8n8.x4.shared.b16 {%0,%1,%2,%3}, [%4];"
                 : "=r"(r0), "=r"(r1), "=r"(r2), "=r"(r3) : "r"(addr));
}
__device__ __forceinline__ void ldmatrix_x2(uint32_t& r0, uint32_t& r1, uint32_t addr) {
    asm volatile("ldmatrix.sync.aligned.m8n8.x2.shared.b16 {%0,%1}, [%2];"
                 : "=r"(r0), "=r"(r1) : "r"(addr));
}
__device__ __forceinline__ void mma_bf16(float& c0, float& c1, float& c2, float& c3,
                                         uint32_t a0, uint32_t a1, uint32_t a2, uint32_t a3,
                                         uint32_t b0, uint32_t b1) {
    asm volatile("mma.sync.aligned.m16n8k16.row.col.f32.bf16.bf16.f32 "
                 "{%0,%1,%2,%3}, {%4,%5,%6,%7}, {%8,%9}, {%0,%1,%2,%3};"
                 : "+f"(c0), "+f"(c1), "+f"(c2), "+f"(c3)
                 : "r"(a0), "r"(a1), "r"(a2), "r"(a3), "r"(b0), "r"(b1));
}
__device__ __forceinline__ void mma_fp16(float& c0, float& c1, float& c2, float& c3,
                                         uint32_t a0, uint32_t a1, uint32_t a2, uint32_t a3,
                                         uint32_t b0, uint32_t b1) {
    asm volatile("mma.sync.aligned.m16n8k16.row.col.f32.f16.f16.f32 "
                 "{%0,%1,%2,%3}, {%4,%5,%6,%7}, {%8,%9}, {%0,%1,%2,%3};"
                 : "+f"(c0), "+f"(c1), "+f"(c2), "+f"(c3)
                 : "r"(a0), "r"(a1), "r"(a2), "r"(a3), "r"(b0), "r"(b1));
}
__device__ __forceinline__ void cp_async16(uint32_t saddr, const void* gptr) {
    asm volatile("cp.async.cg.shared.global [%0], [%1], 16;" :: "r"(saddr), "l"(gptr));
}
#define CP_COMMIT() asm volatile("cp.async.commit_group;" ::: "memory")
#define CP_WAIT0()  asm volatile("cp.async.wait_group 0;" ::: "memory")
#define BAR_SYNC(id, n) asm volatile("bar.sync %0, %1;" :: "r"(id), "r"(n) : "memory")

// ===========================================================================
// Kernel 1: QKV projection as HMMA GEMM (W loaded fp32, cvt in-register).
// grid (L/128, B), 512 threads. Warp w: mg = w&1 (64 l), nh = w>>1 (40 rows).
// Dynamic smem: xs [128][132]u32 (67584B) reused as vt [256][136]bf16 (69632B)
// ===========================================================================
#define QKV_SMEM 69632

__global__ __launch_bounds__(512) void qkv_gemm(
    const float* __restrict__ x,
    const float* __restrict__ Wq, const float* __restrict__ bq,
    const float* __restrict__ Wk, const float* __restrict__ bk,
    const float* __restrict__ Wv, const float* __restrict__ bv)
{
    extern __shared__ __align__(16) char qsmraw[];
    uint32_t* xs = reinterpret_cast<uint32_t*>(qsmraw);

    const int b = blockIdx.y, l0 = blockIdx.x * 128, t = threadIdx.x;
    const float* xb = x + (size_t)b * Cn * Ln;

    // stage x tile as fp16 pairs: xs[l][cp] = {x[2cp][l], x[2cp+1][l]}
    for (int idx = t; idx < 128 * 128; idx += 512) {
        int cp = idx >> 7, l = idx & 127;
        float f0 = xb[(size_t)(2 * cp) * Ln + l0 + l];
        float f1 = xb[(size_t)(2 * cp + 1) * Ln + l0 + l];
        uint32_t p; CVT_F16X2(p, f0, f1);
        xs[l * 132 + cp] = p;
    }
    __syncthreads();

    const int w = t >> 5, lane = t & 31;
    const int mg = w & 1, nh = w >> 1;      // 64 l, 40 rows per warp
    const int nbase = nh * 40;

    // per-nt W source pointers (each 8-row block lies in exactly one matrix)
    const float* wp[5];
    #pragma unroll
    for (int nt = 0; nt < 5; ++nt) {
        int n0 = nbase + nt * 8;
        const float* src;
        if (n0 < 32)      src = Wq + n0 * Cn;
        else if (n0 < 64) src = Wk + (n0 - 64 + 32) * Cn;   // (n0-32)*Cn
        else              src = Wv + (n0 - 64) * Cn;
        wp[nt] = src + (lane >> 2) * Cn + (lane & 3) * 2;
    }

    float of[4][5][4];
    #pragma unroll
    for (int m = 0; m < 4; ++m)
        #pragma unroll
        for (int n = 0; n < 5; ++n)
            #pragma unroll
            for (int k = 0; k < 4; ++k) of[m][n][k] = 0.f;

    const uint32_t abase = smem_to_u32(xs)
        + (uint32_t)((mg * 64 + (lane & 15)) * 132) * 4 + ((lane >> 4) & 1) * 16;

    for (int ks = 0; ks < 16; ++ks) {
        uint32_t aq[4][4];
        #pragma unroll
        for (int mt = 0; mt < 4; ++mt)
            ldmatrix_x4(aq[mt][0], aq[mt][1], aq[mt][2], aq[mt][3],
                        abase + (uint32_t)(mt * 16 * 132) * 4 + ks * 32);
        #pragma unroll
        for (int nt = 0; nt < 5; ++nt) {
            float2 wa = __ldg(reinterpret_cast<const float2*>(wp[nt] + ks * 16));
            float2 wb = __ldg(reinterpret_cast<const float2*>(wp[nt] + ks * 16 + 8));
            uint32_t b0, b1;
            CVT_F16X2(b0, wa.x, wa.y);
            CVT_F16X2(b1, wb.x, wb.y);
            #pragma unroll
            for (int mt = 0; mt < 4; ++mt)
                mma_fp16(of[mt][nt][0], of[mt][nt][1], of[mt][nt][2], of[mt][nt][3],
                         aq[mt][0], aq[mt][1], aq[mt][2], aq[mt][3], b0, b1);
        }
    }
    __syncthreads();   // xs reads done; smem reused for V transpose

    __nv_bfloat16* vt = reinterpret_cast<__nv_bfloat16*>(qsmraw);   // [256][136]
    const float qs = 1.4426950408889634f * 0.17677669529663687f;    // log2e / sqrt(D)

    #pragma unroll
    for (int nt = 0; nt < 5; ++nt) {
        int n0 = nbase + nt * 8;
        int d = n0 + (lane & 3) * 2;
        float2 bs;
        if (n0 < 32)      bs = __ldg(reinterpret_cast<const float2*>(bq + d));
        else if (n0 < 64) bs = __ldg(reinterpret_cast<const float2*>(bk + d - 32));
        else              bs = __ldg(reinterpret_cast<const float2*>(bv + d - 64));
        #pragma unroll
        for (int mt = 0; mt < 4; ++mt) {
            const int ll = mg * 64 + mt * 16 + (lane >> 2);
            const int lq = l0 + ll;
            float v0 = of[mt][nt][0] + bs.x, v1 = of[mt][nt][1] + bs.y;
            float v2 = of[mt][nt][2] + bs.x, v3 = of[mt][nt][3] + bs.y;
            if (n0 < 32) {
                uint32_t p0, p1;
                CVT_BF16X2(p0, v0 * qs, v1 * qs);
                CVT_BF16X2(p1, v2 * qs, v3 * qs);
                *reinterpret_cast<uint32_t*>(&g_Qb[((size_t)b * Ln + lq) * Dn + d])     = p0;
                *reinterpret_cast<uint32_t*>(&g_Qb[((size_t)b * Ln + lq + 8) * Dn + d]) = p1;
            } else if (n0 < 64) {
                int dk = d - 32;
                uint32_t p0, p1;
                CVT_BF16X2(p0, v0, v1);
                CVT_BF16X2(p1, v2, v3);
                *reinterpret_cast<uint32_t*>(&g_Kb[((size_t)b * Ln + lq) * Dn + dk])     = p0;
                *reinterpret_cast<uint32_t*>(&g_Kb[((size_t)b * Ln + lq + 8) * Dn + dk]) = p1;
            } else {
                int c = d - 64;
                vt[c * 136 + ll]           = __float2bfloat16(v0);
                vt[(c + 1) * 136 + ll]     = __float2bfloat16(v1);
                vt[c * 136 + ll + 8]       = __float2bfloat16(v2);
                vt[(c + 1) * 136 + ll + 8] = __float2bfloat16(v3);
            }
        }
    }
    __syncthreads();

    // coalesced V store: [c][l], uint4 along l
    __nv_bfloat16* Vg = g_Vb + (size_t)b * Cn * Ln;
    for (int idx = t; idx < 256 * 16; idx += 512) {
        int c = idx >> 4, k8 = idx & 15;
        *reinterpret_cast<uint4*>(Vg + (size_t)c * Ln + l0 + k8 * 8) =
            *reinterpret_cast<const uint4*>(&vt[c * 136 + k8 * 8]);
    }
}

// ===========================================================================
// Kernel 2: HMMA flash attention. 64 q x 128 ch per CTA, 256 threads,
// 2 CTAs/SM. 128-j chunks, cp.async double-buffered, warp-pair QK dedup.
// grid (L/64, 2, B). Warp w: qg = w>>1 (16 q), ch = w&1 (64 ch / j-half).
// Smem (bytes):
//   [0, 5120)       Q  [64][40] bf16
//   SM_K(bi)        K  [2][128][40] bf16   (10240 each)
//   SM_V(bi)        V  [2][128c][136] bf16 (34816 each; buf0 reused f32 [64][68])
//   SM_P + w*2048   P exchange slots (8 x 2048)
//   SM_LS + w*256   row-sum exchange (8 x 256)
// ===========================================================================
#define SM_K(bi) (5120 + (bi) * 10240)
#define SM_V(bi) (25600 + (bi) * 34816)
#define SM_P     95232
#define SM_LS    111616
#define SM_TOTAL 113664

__global__ __launch_bounds__(256, 2) void attn_kernel(
    const float* __restrict__ x,
    const float* __restrict__ gamma,
    float* __restrict__ out)
{
    extern __shared__ __align__(16) char dsm[];
    const int b = blockIdx.z, ch_half = blockIdx.y, i0 = blockIdx.x * 64;
    const int t = threadIdx.x;
    const int w = t >> 5, lane = t & 31;
    const int qg = w >> 1, ch = w & 1;

    const uint32_t sbase = smem_to_u32(dsm);
    __nv_bfloat16* Qsm = reinterpret_cast<__nv_bfloat16*>(dsm);

    const __nv_bfloat16* Qg = &g_Qb[((size_t)b * Ln + i0) * Dn];
    const __nv_bfloat16* Kg = &g_Kb[(size_t)b * Ln * Dn];
    const __nv_bfloat16* Vg = &g_Vb[((size_t)b * Cn + ch_half * 128) * Ln];

    // stage Q tile: 64 q x 32 d (256 x uint4)
    {
        int q = t >> 2, dc = t & 3;
        uint4 v = *reinterpret_cast<const uint4*>(Qg + (size_t)q * Dn + dc * 8);
        *reinterpret_cast<uint4*>(&Qsm[q * 40 + dc * 8]) = v;
    }

    // prologue: chunk 0. K: 512 cp (2/thread); V: 2048 cp (8/thread)
    {
        #pragma unroll
        for (int i = 0; i < 2; ++i) {
            int idx = t + i * 256;
            int j = idx >> 2, dc = idx & 3;
            cp_async16(sbase + SM_K(0) + j * 80 + dc * 16, Kg + (size_t)j * Dn + dc * 8);
        }
        #pragma unroll
        for (int i = 0; i < 8; ++i) {
            int idx = t + i * 256;
            int c = idx >> 4, jc = idx & 15;
            cp_async16(sbase + SM_V(0) + c * 272 + jc * 16, Vg + (size_t)c * Ln + jc * 8);
        }
    }
    CP_COMMIT();
    __syncthreads();

    // Q a-frags, loaded once
    uint32_t aq[2][4];
    {
        uint32_t base = sbase + ((qg * 16 + (lane & 15)) * 40 + ((lane >> 4) & 1) * 8) * 2;
        ldmatrix_x4(aq[0][0], aq[0][1], aq[0][2], aq[0][3], base);
        ldmatrix_x4(aq[1][0], aq[1][1], aq[1][2], aq[1][3], base + 32);
    }

    const uint32_t kb_lane = (lane & 7) * 80 + ((lane >> 3) & 1) * 16;
    const uint32_t vb_lane = (lane & 7) * 272 + (lane >> 3) * 16;
    const uint32_t myslot  = SM_P + w * 2048 + lane * 16;
    const uint32_t pairbase= SM_P + (qg * 2) * 2048 + lane * 16;   // + h*2048 = warp (qg*2+h)
    const int barid = 1 + qg;

    float of[8][4];
    #pragma unroll
    for (int n = 0; n < 8; ++n)
        #pragma unroll
        for (int k = 0; k < 4; ++k) of[n][k] = 0.f;
    float lsum0 = 0.f, lsum1 = 0.f;

    for (int cidx = 0; cidx < Ln / 128; ++cidx) {
        CP_WAIT0();
        __syncthreads();

        // issue chunk cidx+1
        if (cidx + 1 < Ln / 128) {
            int j0n = (cidx + 1) * 128;
            int bi = (cidx + 1) & 1;
            #pragma unroll
            for (int i = 0; i < 2; ++i) {
                int idx = t + i * 256;
                int j = idx >> 2, dc = idx & 3;
                cp_async16(sbase + SM_K(bi) + j * 80 + dc * 16,
                           Kg + (size_t)(j0n + j) * Dn + dc * 8);
            }
            #pragma unroll
            for (int i = 0; i < 8; ++i) {
                int idx = t + i * 256;
                int c = idx >> 4, jc = idx & 15;
                cp_async16(sbase + SM_V(bi) + c * 272 + jc * 16,
                           Vg + (size_t)c * Ln + j0n + jc * 8);
            }
        }
        CP_COMMIT();

        const uint32_t ks_u = sbase + SM_K(cidx & 1);
        const uint32_t vs_u = sbase + SM_V(cidx & 1);

        // S = Q K^T for MY 64-j half -> exp -> pa
        uint32_t pa[4][4];
        {
            const uint32_t kh = ks_u + (uint32_t)(ch * 64) * 80 + kb_lane;
            #pragma unroll
            for (int jt = 0; jt < 8; ++jt) {
                float s0 = 0.f, s1 = 0.f, s2 = 0.f, s3 = 0.f;
                uint32_t b0, b1;
                uint32_t kaddr = kh + jt * 640;
                ldmatrix_x2(b0, b1, kaddr);
                mma_bf16(s0, s1, s2, s3, aq[0][0], aq[0][1], aq[0][2], aq[0][3], b0, b1);
                ldmatrix_x2(b0, b1, kaddr + 32);
                mma_bf16(s0, s1, s2, s3, aq[1][0], aq[1][1], aq[1][2], aq[1][3], b0, b1);

                float e0 = ex2f(s0), e1 = ex2f(s1), e2 = ex2f(s2), e3 = ex2f(s3);
                lsum0 += e0 + e1;
                lsum1 += e2 + e3;
                uint32_t plo, phi;
                CVT_BF16X2(plo, e0, e1);
                CVT_BF16X2(phi, e2, e3);
                int pt = jt >> 1;
                if ((jt & 1) == 0) { pa[pt][0] = plo; pa[pt][1] = phi; }
                else               { pa[pt][2] = plo; pa[pt][3] = phi; }
            }
        }
        // publish my P frags
        #pragma unroll
        for (int pt = 0; pt < 4; ++pt)
            *reinterpret_cast<uint4*>(dsm + myslot + pt * 512) =
                make_uint4(pa[pt][0], pa[pt][1], pa[pt][2], pa[pt][3]);

        // PV own j-half first (no wait on pair)
        #pragma unroll
        for (int nt = 0; nt < 8; ++nt) {
            uint32_t vbase = vs_u + (uint32_t)(ch * 64 + nt * 8) * 272 + ch * 128 + vb_lane;
            uint32_t b0, b1, b2, b3;
            ldmatrix_x4(b0, b1, b2, b3, vbase);
            mma_bf16(of[nt][0], of[nt][1], of[nt][2], of[nt][3],
                     pa[0][0], pa[0][1], pa[0][2], pa[0][3], b0, b1);
            mma_bf16(of[nt][0], of[nt][1], of[nt][2], of[nt][3],
                     pa[1][0], pa[1][1], pa[1][2], pa[1][3], b2, b3);
            ldmatrix_x4(b0, b1, b2, b3, vbase + 64);
            mma_bf16(of[nt][0], of[nt][1], of[nt][2], of[nt][3],
                     pa[2][0], pa[2][1], pa[2][2], pa[2][3], b0, b1);
            mma_bf16(of[nt][0], of[nt][1], of[nt][2], of[nt][3],
                     pa[3][0], pa[3][1], pa[3][2], pa[3][3], b2, b3);
        }
        BAR_SYNC(barid, 64);

        // PV other j-half with pair's P
        {
            const int h = ch ^ 1;
            uint32_t pf[4][4];
            #pragma unroll
            for (int pt = 0; pt < 4; ++pt) {
                uint4 v = *reinterpret_cast<const uint4*>(dsm + pairbase + h * 2048 + pt * 512);
                pf[pt][0] = v.x; pf[pt][1] = v.y; pf[pt][2] = v.z; pf[pt][3] = v.w;
            }
            #pragma unroll
            for (int nt = 0; nt < 8; ++nt) {
                uint32_t vbase = vs_u + (uint32_t)(ch * 64 + nt * 8) * 272 + h * 128 + vb_lane;
                uint32_t b0, b1, b2, b3;
                ldmatrix_x4(b0, b1, b2, b3, vbase);
                mma_bf16(of[nt][0], of[nt][1], of[nt][2], of[nt][3],
                         pf[0][0], pf[0][1], pf[0][2], pf[0][3], b0, b1);
                mma_bf16(of[nt][0], of[nt][1], of[nt][2], of[nt][3],
                         pf[1][0], pf[1][1], pf[1][2], pf[1][3], b2, b3);
                ldmatrix_x4(b0, b1, b2, b3, vbase + 64);
                mma_bf16(of[nt][0], of[nt][1], of[nt][2], of[nt][3],
                         pf[2][0], pf[2][1], pf[2][2], pf[2][3], b0, b1);
                mma_bf16(of[nt][0], of[nt][1], of[nt][2], of[nt][3],
                         pf[3][0], pf[3][1], pf[3][2], pf[3][3], b2, b3);
            }
        }
    }

    // row sums: quad-reduce, combine across warp pair
    lsum0 += __shfl_xor_sync(0xFFFFFFFF, lsum0, 1);
    lsum0 += __shfl_xor_sync(0xFFFFFFFF, lsum0, 2);
    lsum1 += __shfl_xor_sync(0xFFFFFFFF, lsum1, 1);
    lsum1 += __shfl_xor_sync(0xFFFFFFFF, lsum1, 2);
    {
        float2* ls = reinterpret_cast<float2*>(dsm + SM_LS + w * 256);
        ls[lane] = make_float2(lsum0, lsum1);
        BAR_SYNC(barid, 64);
        const float2* lsp = reinterpret_cast<const float2*>(dsm + SM_LS + (w ^ 1) * 256);
        float2 o = lsp[lane];
        lsum0 += o.x;
        lsum1 += o.y;
    }
    const float linv0 = 1.f / lsum0;
    const float linv1 = 1.f / lsum1;
    const float gam = __ldg(gamma);

    float* Tsm = reinterpret_cast<float*>(dsm + SM_V(0));   // [64][68] f32
    const float* xb = x + (size_t)b * Cn * Ln;
    float* ob = out + (size_t)b * Cn * Ln;

    for (int h = 0; h < 2; ++h) {
        __syncthreads();
        if (ch == h) {
            int q = qg * 16 + (lane >> 2);
            #pragma unroll
            for (int nt = 0; nt < 8; ++nt) {
                int cl = nt * 8 + (lane & 3) * 2;
                Tsm[cl * 68 + q]           = of[nt][0] * linv0;
                Tsm[(cl + 1) * 68 + q]     = of[nt][1] * linv0;
                Tsm[cl * 68 + q + 8]       = of[nt][2] * linv1;
                Tsm[(cl + 1) * 68 + q + 8] = of[nt][3] * linv1;
            }
        }
        __syncthreads();
        for (int idx = t; idx < 64 * 64; idx += 256) {
            int cl = idx >> 6, q = idx & 63;
            size_t off = (size_t)(ch_half * 128 + h * 64 + cl) * Ln + i0 + q;
            ob[off] = gam * Tsm[cl * 68 + q] + xb[off];
        }
    }
}

// ===========================================================================
extern "C" void kernel_launch(void* const* d_in, const int* in_sizes, int n_in,
                              void* d_out, int out_size)
{
    const float* x     = (const float*)d_in[0];
    const float* Wq    = (const float*)d_in[1];
    const float* bq    = (const float*)d_in[2];
    const float* Wk    = (const float*)d_in[3];
    const float* bk    = (const float*)d_in[4];
    const float* Wv    = (const float*)d_in[5];
    const float* bv    = (const float*)d_in[6];
    const float* gamma = (const float*)d_in[7];
    float* out = (float*)d_out;

    cudaFuncSetAttribute(qkv_gemm, cudaFuncAttributeMaxDynamicSharedMemorySize, QKV_SMEM);
    cudaFuncSetAttribute(attn_kernel, cudaFuncAttributeMaxDynamicSharedMemorySize, SM_TOTAL);

    qkv_gemm<<<dim3(Ln / 128, Bn), 512, QKV_SMEM>>>(x, Wq, bq, Wk, bk, Wv, bv);
    attn_kernel<<<dim3(Ln / 64, 2, Bn), 256, SM_TOTAL>>>(x, gamma, out);
}

// round 10
// speedup vs baseline: 11.3774x; 1.0970x over previous
#include <cuda_runtime.h>
#include <cuda_bf16.h>
#include <cuda_fp16.h>
#include <cstdint>

#define Bn 8
#define Cn 256
#define Ln 2048
#define Dn 32

// scratch (device globals; no cudaMalloc allowed)
__device__ __nv_bfloat16 g_Qb[Bn * Ln * Dn];   // [b][l][d]  pre-scaled by scale*log2e
__device__ __nv_bfloat16 g_Kb[Bn * Ln * Dn];   // [b][l][d]
__device__ __nv_bfloat16 g_Vb[Bn * Cn * Ln];   // [b][c][l]

// ============================ helpers ======================================
__device__ __forceinline__ uint32_t smem_to_u32(const void* p) {
    uint32_t a;
    asm("{ .reg .u64 t; cvta.to.shared.u64 t, %1; cvt.u32.u64 %0, t; }" : "=r"(a) : "l"(p));
    return a;
}
__device__ __forceinline__ float ex2f(float x) {
    float r; asm("ex2.approx.ftz.f32 %0, %1;" : "=f"(r) : "f"(x)); return r;
}
#define CVT_BF16X2(res, a, b) \
    asm("cvt.rn.bf16x2.f32 %0, %1, %2;" : "=r"(res) : "f"(b), "f"(a))
#define CVT_F16X2(res, a, b) \
    asm("cvt.rn.f16x2.f32 %0, %1, %2;" : "=r"(res) : "f"(b), "f"(a))

__device__ __forceinline__ void ldmatrix_x4(uint32_t& r0, uint32_t& r1, uint32_t& r2, uint32_t& r3, uint32_t addr) {
    asm volatile("ldmatrix.sync.aligned.m8n8.x4.shared.b16 {%0,%1,%2,%3}, [%4];"
                 : "=r"(r0), "=r"(r1), "=r"(r2), "=r"(r3) : "r"(addr));
}
__device__ __forceinline__ void ldmatrix_x2(uint32_t& r0, uint32_t& r1, uint32_t addr) {
    asm volatile("ldmatrix.sync.aligned.m8n8.x2.shared.b16 {%0,%1}, [%2];"
                 : "=r"(r0), "=r"(r1) : "r"(addr));
}
__device__ __forceinline__ void mma_bf16(float& c0, float& c1, float& c2, float& c3,
                                         uint32_t a0, uint32_t a1, uint32_t a2, uint32_t a3,
                                         uint32_t b0, uint32_t b1) {
    asm volatile("mma.sync.aligned.m16n8k16.row.col.f32.bf16.bf16.f32 "
                 "{%0,%1,%2,%3}, {%4,%5,%6,%7}, {%8,%9}, {%0,%1,%2,%3};"
                 : "+f"(c0), "+f"(c1), "+f"(c2), "+f"(c3)
                 : "r"(a0), "r"(a1), "r"(a2), "r"(a3), "r"(b0), "r"(b1));
}
__device__ __forceinline__ void mma_fp16(float& c0, float& c1, float& c2, float& c3,
                                         uint32_t a0, uint32_t a1, uint32_t a2, uint32_t a3,
                                         uint32_t b0, uint32_t b1) {
    asm volatile("mma.sync.aligned.m16n8k16.row.col.f32.f16.f16.f32 "
                 "{%0,%1,%2,%3}, {%4,%5,%6,%7}, {%8,%9}, {%0,%1,%2,%3};"
                 : "+f"(c0), "+f"(c1), "+f"(c2), "+f"(c3)
                 : "r"(a0), "r"(a1), "r"(a2), "r"(a3), "r"(b0), "r"(b1));
}
__device__ __forceinline__ void cp_async16(uint32_t saddr, const void* gptr) {
    asm volatile("cp.async.cg.shared.global [%0], [%1], 16;" :: "r"(saddr), "l"(gptr));
}
#define CP_COMMIT() asm volatile("cp.async.commit_group;" ::: "memory")
#define CP_WAIT0()  asm volatile("cp.async.wait_group 0;" ::: "memory")
#define BAR_SYNC(id, n) asm volatile("bar.sync %0, %1;" :: "r"(id), "r"(n) : "memory")

// ===========================================================================
// Kernel 1: QKV projection as HMMA GEMM (unchanged from R9).
// grid (L/128, B), 512 threads. Warp w: mg = w&1 (64 l), nh = w>>1 (40 rows).
// ===========================================================================
#define QKV_SMEM 69632

__global__ __launch_bounds__(512) void qkv_gemm(
    const float* __restrict__ x,
    const float* __restrict__ Wq, const float* __restrict__ bq,
    const float* __restrict__ Wk, const float* __restrict__ bk,
    const float* __restrict__ Wv, const float* __restrict__ bv)
{
    extern __shared__ __align__(16) char qsmraw[];
    uint32_t* xs = reinterpret_cast<uint32_t*>(qsmraw);

    const int b = blockIdx.y, l0 = blockIdx.x * 128, t = threadIdx.x;
    const float* xb = x + (size_t)b * Cn * Ln;

    for (int idx = t; idx < 128 * 128; idx += 512) {
        int cp = idx >> 7, l = idx & 127;
        float f0 = xb[(size_t)(2 * cp) * Ln + l0 + l];
        float f1 = xb[(size_t)(2 * cp + 1) * Ln + l0 + l];
        uint32_t p; CVT_F16X2(p, f0, f1);
        xs[l * 132 + cp] = p;
    }
    __syncthreads();

    const int w = t >> 5, lane = t & 31;
    const int mg = w & 1, nh = w >> 1;
    const int nbase = nh * 40;

    const float* wp[5];
    #pragma unroll
    for (int nt = 0; nt < 5; ++nt) {
        int n0 = nbase + nt * 8;
        const float* src;
        if (n0 < 32)      src = Wq + n0 * Cn;
        else if (n0 < 64) src = Wk + (n0 - 32) * Cn;
        else              src = Wv + (n0 - 64) * Cn;
        wp[nt] = src + (lane >> 2) * Cn + (lane & 3) * 2;
    }

    float of[4][5][4];
    #pragma unroll
    for (int m = 0; m < 4; ++m)
        #pragma unroll
        for (int n = 0; n < 5; ++n)
            #pragma unroll
            for (int k = 0; k < 4; ++k) of[m][n][k] = 0.f;

    const uint32_t abase = smem_to_u32(xs)
        + (uint32_t)((mg * 64 + (lane & 15)) * 132) * 4 + ((lane >> 4) & 1) * 16;

    for (int ks = 0; ks < 16; ++ks) {
        uint32_t aq[4][4];
        #pragma unroll
        for (int mt = 0; mt < 4; ++mt)
            ldmatrix_x4(aq[mt][0], aq[mt][1], aq[mt][2], aq[mt][3],
                        abase + (uint32_t)(mt * 16 * 132) * 4 + ks * 32);
        #pragma unroll
        for (int nt = 0; nt < 5; ++nt) {
            float2 wa = __ldg(reinterpret_cast<const float2*>(wp[nt] + ks * 16));
            float2 wb = __ldg(reinterpret_cast<const float2*>(wp[nt] + ks * 16 + 8));
            uint32_t b0, b1;
            CVT_F16X2(b0, wa.x, wa.y);
            CVT_F16X2(b1, wb.x, wb.y);
            #pragma unroll
            for (int mt = 0; mt < 4; ++mt)
                mma_fp16(of[mt][nt][0], of[mt][nt][1], of[mt][nt][2], of[mt][nt][3],
                         aq[mt][0], aq[mt][1], aq[mt][2], aq[mt][3], b0, b1);
        }
    }
    __syncthreads();

    __nv_bfloat16* vt = reinterpret_cast<__nv_bfloat16*>(qsmraw);   // [256][136]
    const float qs = 1.4426950408889634f * 0.17677669529663687f;    // log2e / sqrt(D)

    #pragma unroll
    for (int nt = 0; nt < 5; ++nt) {
        int n0 = nbase + nt * 8;
        int d = n0 + (lane & 3) * 2;
        float2 bs;
        if (n0 < 32)      bs = __ldg(reinterpret_cast<const float2*>(bq + d));
        else if (n0 < 64) bs = __ldg(reinterpret_cast<const float2*>(bk + d - 32));
        else              bs = __ldg(reinterpret_cast<const float2*>(bv + d - 64));
        #pragma unroll
        for (int mt = 0; mt < 4; ++mt) {
            const int ll = mg * 64 + mt * 16 + (lane >> 2);
            const int lq = l0 + ll;
            float v0 = of[mt][nt][0] + bs.x, v1 = of[mt][nt][1] + bs.y;
            float v2 = of[mt][nt][2] + bs.x, v3 = of[mt][nt][3] + bs.y;
            if (n0 < 32) {
                uint32_t p0, p1;
                CVT_BF16X2(p0, v0 * qs, v1 * qs);
                CVT_BF16X2(p1, v2 * qs, v3 * qs);
                *reinterpret_cast<uint32_t*>(&g_Qb[((size_t)b * Ln + lq) * Dn + d])     = p0;
                *reinterpret_cast<uint32_t*>(&g_Qb[((size_t)b * Ln + lq + 8) * Dn + d]) = p1;
            } else if (n0 < 64) {
                int dk = d - 32;
                uint32_t p0, p1;
                CVT_BF16X2(p0, v0, v1);
                CVT_BF16X2(p1, v2, v3);
                *reinterpret_cast<uint32_t*>(&g_Kb[((size_t)b * Ln + lq) * Dn + dk])     = p0;
                *reinterpret_cast<uint32_t*>(&g_Kb[((size_t)b * Ln + lq + 8) * Dn + dk]) = p1;
            } else {
                int c = d - 64;
                vt[c * 136 + ll]           = __float2bfloat16(v0);
                vt[(c + 1) * 136 + ll]     = __float2bfloat16(v1);
                vt[c * 136 + ll + 8]       = __float2bfloat16(v2);
                vt[(c + 1) * 136 + ll + 8] = __float2bfloat16(v3);
            }
        }
    }
    __syncthreads();

    __nv_bfloat16* Vg = g_Vb + (size_t)b * Cn * Ln;
    for (int idx = t; idx < 256 * 16; idx += 512) {
        int c = idx >> 4, k8 = idx & 15;
        *reinterpret_cast<uint4*>(Vg + (size_t)c * Ln + l0 + k8 * 8) =
            *reinterpret_cast<const uint4*>(&vt[c * 136 + k8 * 8]);
    }
}

// ===========================================================================
// Kernel 2: HMMA flash attention, TWO 64-q blocks per CTA, single wave.
// grid (L/128, 2, B) = 256 CTAs, 256 threads, 2 CTAs/SM.
// Warp w: qg = w>>1 (16 q rows within each q-block), ch = w&1 (64 ch / j-half).
// Smem (bytes):
//   [0, 16384)      prologue Q [128][40] bf16 (10240)  /  main-loop P slots (8 x 2048)
//   SM_K(bi)        K [2][128][40] bf16   (10240 each)
//   SM_V(bi)        V [2][128c][136el] bf16 (34816 each; buf0 reused f32 [64][68] epilogue)
//   SM_LS           row-sum exchange (8 warps x 2 qt x 256B = 4096)
// ===========================================================================
#define SM_PQ    0
#define SM_K(bi) (16384 + (bi) * 10240)
#define SM_V(bi) (36864 + (bi) * 34816)
#define SM_LS    106496
#define SM_TOTAL 110592

__global__ __launch_bounds__(256, 2) void attn_kernel(
    const float* __restrict__ x,
    const float* __restrict__ gamma,
    float* __restrict__ out)
{
    extern __shared__ __align__(16) char dsm[];
    const int b = blockIdx.z, ch_half = blockIdx.y, i0 = blockIdx.x * 128;
    const int t = threadIdx.x;
    const int w = t >> 5, lane = t & 31;
    const int qg = w >> 1, ch = w & 1;

    const uint32_t sbase = smem_to_u32(dsm);
    __nv_bfloat16* Qsm = reinterpret_cast<__nv_bfloat16*>(dsm + SM_PQ);

    const __nv_bfloat16* Qg = &g_Qb[((size_t)b * Ln + i0) * Dn];
    const __nv_bfloat16* Kg = &g_Kb[(size_t)b * Ln * Dn];
    const __nv_bfloat16* Vg = &g_Vb[((size_t)b * Cn + ch_half * 128) * Ln];

    // stage Q tile: 128 q x 32 d (512 uint4, 2/thread)
    #pragma unroll
    for (int i = 0; i < 2; ++i) {
        int idx = t + i * 256;
        int q = idx >> 2, dc = idx & 3;
        uint4 v = *reinterpret_cast<const uint4*>(Qg + (size_t)q * Dn + dc * 8);
        *reinterpret_cast<uint4*>(&Qsm[q * 40 + dc * 8]) = v;
    }

    // prologue: chunk 0. K: 512 cp (2/thread); V: 2048 cp (8/thread)
    {
        #pragma unroll
        for (int i = 0; i < 2; ++i) {
            int idx = t + i * 256;
            int j = idx >> 2, dc = idx & 3;
            cp_async16(sbase + SM_K(0) + j * 80 + dc * 16, Kg + (size_t)j * Dn + dc * 8);
        }
        #pragma unroll
        for (int i = 0; i < 8; ++i) {
            int idx = t + i * 256;
            int c = idx >> 4, jc = idx & 15;
            cp_async16(sbase + SM_V(0) + c * 272 + jc * 16, Vg + (size_t)c * Ln + jc * 8);
        }
    }
    CP_COMMIT();
    __syncthreads();

    // Q a-frags for both q-tiles (Q smem dead afterwards -> region becomes P slots)
    uint32_t aq[2][2][4];
    #pragma unroll
    for (int qt = 0; qt < 2; ++qt) {
        uint32_t base = sbase + SM_PQ
            + ((qt * 64 + qg * 16 + (lane & 15)) * 40 + ((lane >> 4) & 1) * 8) * 2;
        ldmatrix_x4(aq[qt][0][0], aq[qt][0][1], aq[qt][0][2], aq[qt][0][3], base);
        ldmatrix_x4(aq[qt][1][0], aq[qt][1][1], aq[qt][1][2], aq[qt][1][3], base + 32);
    }

    const uint32_t kb_lane = (lane & 7) * 80 + ((lane >> 3) & 1) * 16;
    const uint32_t vb_lane = (lane & 7) * 272 + (lane >> 3) * 16;
    const uint32_t myslot  = SM_PQ + w * 2048 + lane * 16;
    const uint32_t pairslot = SM_PQ + (uint32_t)(qg * 2 + (ch ^ 1)) * 2048 + lane * 16;
    const int barid = 1 + qg;

    float of[2][8][4];
    #pragma unroll
    for (int qt = 0; qt < 2; ++qt)
        #pragma unroll
        for (int n = 0; n < 8; ++n)
            #pragma unroll
            for (int k = 0; k < 4; ++k) of[qt][n][k] = 0.f;
    float lsum[2][2] = {{0.f, 0.f}, {0.f, 0.f}};

// QK for q-tile QT over own 64-j half -> pa + lsum, then STS to my slot
#define QK_PHASE(QT) do {                                                      \
    const uint32_t kh = ks_u + (uint32_t)(ch * 64) * 80 + kb_lane;             \
    _Pragma("unroll")                                                          \
    for (int jt = 0; jt < 8; ++jt) {                                           \
        float s0 = 0.f, s1 = 0.f, s2 = 0.f, s3 = 0.f;                          \
        uint32_t b0, b1;                                                       \
        uint32_t kaddr = kh + jt * 640;                                        \
        ldmatrix_x2(b0, b1, kaddr);                                            \
        mma_bf16(s0, s1, s2, s3, aq[QT][0][0], aq[QT][0][1],                   \
                 aq[QT][0][2], aq[QT][0][3], b0, b1);                          \
        ldmatrix_x2(b0, b1, kaddr + 32);                                       \
        mma_bf16(s0, s1, s2, s3, aq[QT][1][0], aq[QT][1][1],                   \
                 aq[QT][1][2], aq[QT][1][3], b0, b1);                          \
        float e0 = ex2f(s0), e1 = ex2f(s1), e2 = ex2f(s2), e3 = ex2f(s3);      \
        lsum[QT][0] += e0 + e1;                                                \
        lsum[QT][1] += e2 + e3;                                                \
        uint32_t plo, phi;                                                     \
        CVT_BF16X2(plo, e0, e1);                                               \
        CVT_BF16X2(phi, e2, e3);                                               \
        int pt = jt >> 1;                                                      \
        if ((jt & 1) == 0) { pa[pt][0] = plo; pa[pt][1] = phi; }               \
        else               { pa[pt][2] = plo; pa[pt][3] = phi; }               \
    }                                                                          \
    _Pragma("unroll")                                                          \
    for (int pt = 0; pt < 4; ++pt)                                             \
        *reinterpret_cast<uint4*>(dsm + myslot + pt * 512) =                   \
            make_uint4(pa[pt][0], pa[pt][1], pa[pt][2], pa[pt][3]);            \
} while (0)

// PV for q-tile QT, j-half H, with fragment array PF
#define PV_PHASE(QT, H, PF) do {                                               \
    _Pragma("unroll")                                                          \
    for (int nt = 0; nt < 8; ++nt) {                                           \
        uint32_t vbase = vs_u + (uint32_t)(ch * 64 + nt * 8) * 272             \
                       + (H) * 128 + vb_lane;                                  \
        uint32_t b0, b1, b2, b3;                                               \
        ldmatrix_x4(b0, b1, b2, b3, vbase);                                    \
        mma_bf16(of[QT][nt][0], of[QT][nt][1], of[QT][nt][2], of[QT][nt][3],   \
                 PF[0][0], PF[0][1], PF[0][2], PF[0][3], b0, b1);              \
        mma_bf16(of[QT][nt][0], of[QT][nt][1], of[QT][nt][2], of[QT][nt][3],   \
                 PF[1][0], PF[1][1], PF[1][2], PF[1][3], b2, b3);              \
        ldmatrix_x4(b0, b1, b2, b3, vbase + 64);                               \
        mma_bf16(of[QT][nt][0], of[QT][nt][1], of[QT][nt][2], of[QT][nt][3],   \
                 PF[2][0], PF[2][1], PF[2][2], PF[2][3], b0, b1);              \
        mma_bf16(of[QT][nt][0], of[QT][nt][1], of[QT][nt][2], of[QT][nt][3],   \
                 PF[3][0], PF[3][1], PF[3][2], PF[3][3], b2, b3);              \
    }                                                                          \
} while (0)

#define LOAD_PAIR_P(PF) do {                                                   \
    _Pragma("unroll")                                                          \
    for (int pt = 0; pt < 4; ++pt) {                                           \
        uint4 v = *reinterpret_cast<const uint4*>(dsm + pairslot + pt * 512);  \
        PF[pt][0] = v.x; PF[pt][1] = v.y; PF[pt][2] = v.z; PF[pt][3] = v.w;    \
    }                                                                          \
} while (0)

    for (int cidx = 0; cidx < Ln / 128; ++cidx) {
        CP_WAIT0();
        __syncthreads();   // buffers + P slots free for this chunk

        // issue chunk cidx+1
        if (cidx + 1 < Ln / 128) {
            int j0n = (cidx + 1) * 128;
            int bi = (cidx + 1) & 1;
            #pragma unroll
            for (int i = 0; i < 2; ++i) {
                int idx = t + i * 256;
                int j = idx >> 2, dc = idx & 3;
                cp_async16(sbase + SM_K(bi) + j * 80 + dc * 16,
                           Kg + (size_t)(j0n + j) * Dn + dc * 8);
            }
            #pragma unroll
            for (int i = 0; i < 8; ++i) {
                int idx = t + i * 256;
                int c = idx >> 4, jc = idx & 15;
                cp_async16(sbase + SM_V(bi) + c * 272 + jc * 16,
                           Vg + (size_t)c * Ln + j0n + jc * 8);
            }
        }
        CP_COMMIT();

        const uint32_t ks_u = sbase + SM_K(cidx & 1);
        const uint32_t vs_u = sbase + SM_V(cidx & 1);

        uint32_t pa[4][4], pf[4][4];

        // --- q-tile 0 ---
        QK_PHASE(0);
        PV_PHASE(0, ch, pa);          // own j-half
        BAR_SYNC(barid, 64);          // pa0 published by both warps of pair
        LOAD_PAIR_P(pf);
        BAR_SYNC(barid, 64);          // pf0 consumed -> slot may be overwritten
        PV_PHASE(0, ch ^ 1, pf);      // other j-half

        // --- q-tile 1 ---
        QK_PHASE(1);
        PV_PHASE(1, ch, pa);
        BAR_SYNC(barid, 64);          // pa1 published
        LOAD_PAIR_P(pf);
        PV_PHASE(1, ch ^ 1, pf);
        // next overwrite of slots is after the loop-top __syncthreads
    }

    const float gam = __ldg(gamma);
    const float* xb = x + (size_t)b * Cn * Ln;
    float* ob = out + (size_t)b * Cn * Ln;
    float* Tsm = reinterpret_cast<float*>(dsm + SM_V(0));   // [64][68] f32

    #pragma unroll
    for (int qt = 0; qt < 2; ++qt) {
        // row sums: quad-reduce, combine across warp pair
        float l0s = lsum[qt][0], l1s = lsum[qt][1];
        l0s += __shfl_xor_sync(0xFFFFFFFF, l0s, 1);
        l0s += __shfl_xor_sync(0xFFFFFFFF, l0s, 2);
        l1s += __shfl_xor_sync(0xFFFFFFFF, l1s, 1);
        l1s += __shfl_xor_sync(0xFFFFFFFF, l1s, 2);
        {
            float2* ls = reinterpret_cast<float2*>(dsm + SM_LS + (w * 2 + qt) * 256);
            ls[lane] = make_float2(l0s, l1s);
            BAR_SYNC(barid, 64);
            const float2* lsp = reinterpret_cast<const float2*>(
                dsm + SM_LS + ((w ^ 1) * 2 + qt) * 256);
            float2 o = lsp[lane];
            l0s += o.x;
            l1s += o.y;
        }
        const float linv0 = 1.f / l0s;
        const float linv1 = 1.f / l1s;

        for (int h = 0; h < 2; ++h) {
            __syncthreads();
            if (ch == h) {
                int q = qg * 16 + (lane >> 2);
                #pragma unroll
                for (int nt = 0; nt < 8; ++nt) {
                    int cl = nt * 8 + (lane & 3) * 2;
                    Tsm[cl * 68 + q]           = of[qt][nt][0] * linv0;
                    Tsm[(cl + 1) * 68 + q]     = of[qt][nt][1] * linv0;
                    Tsm[cl * 68 + q + 8]       = of[qt][nt][2] * linv1;
                    Tsm[(cl + 1) * 68 + q + 8] = of[qt][nt][3] * linv1;
                }
            }
            __syncthreads();
            for (int idx = t; idx < 64 * 64; idx += 256) {
                int cl = idx >> 6, q = idx & 63;
                size_t off = (size_t)(ch_half * 128 + h * 64 + cl) * Ln + i0 + qt * 64 + q;
                ob[off] = gam * Tsm[cl * 68 + q] + xb[off];
            }
        }
    }
}

// ===========================================================================
extern "C" void kernel_launch(void* const* d_in, const int* in_sizes, int n_in,
                              void* d_out, int out_size)
{
    const float* x     = (const float*)d_in[0];
    const float* Wq    = (const float*)d_in[1];
    const float* bq    = (const float*)d_in[2];
    const float* Wk    = (const float*)d_in[3];
    const float* bk    = (const float*)d_in[4];
    const float* Wv    = (const float*)d_in[5];
    const float* bv    = (const float*)d_in[6];
    const float* gamma = (const float*)d_in[7];
    float* out = (float*)d_out;

    cudaFuncSetAttribute(qkv_gemm, cudaFuncAttributeMaxDynamicSharedMemorySize, QKV_SMEM);
    cudaFuncSetAttribute(attn_kernel, cudaFuncAttributeMaxDynamicSharedMemorySize, SM_TOTAL);

    qkv_gemm<<<dim3(Ln / 128, Bn), 512, QKV_SMEM>>>(x, Wq, bq, Wk, bk, Wv, bv);
    attn_kernel<<<dim3(Ln / 128, 2, Bn), 256, SM_TOTAL>>>(x, gamma, out);
}